// round 11
// baseline (speedup 1.0000x reference)
#include <cuda_runtime.h>
#include <cuda_bf16.h>
#include <cstdint>

#define BSZ  1024
#define TT   32
#define AD   224
#define HID  256
#define VOCAB 29
#define OUT_LEN 25

// ---------------- scratch (device globals) ----------------
__device__ float g_y1[BSZ*4*192*28];
__device__ float g_y2[BSZ*16*96*14];
__device__ float g_y3[BSZ*16*32*7];
__device__ float g_y5[BSZ*TT*AD];
__device__ __align__(16) float g_xW[BSZ*TT*896];
__device__ __align__(16) float g_y8[BSZ*TT*AD];
__device__ float g_escore[BSZ*TT];
__device__ float g_c [BSZ*AD];
__device__ float g_dh[BSZ*HID];
__device__ float g_dc[BSZ*HID];
// pre-split activations (bf16 hi/lo pairs packed as u32)
__device__ __align__(16) uint32_t g_Y5h[BSZ*TT*112], g_Y5l[BSZ*TT*112];
__device__ __align__(16) uint32_t g_Hh[2*BSZ*112],   g_Hl[2*BSZ*112];
__device__ __align__(16) uint32_t g_Ch[2*BSZ*240],   g_Cl[2*BSZ*240];
// pre-split weights, gate-interleaved rows
__device__ __align__(16) uint32_t g_WihH[896*112], g_WihL[896*112];
__device__ __align__(16) uint32_t g_WhhH[896*112], g_WhhL[896*112];
__device__ __align__(16) uint32_t g_WdH[1024*240], g_WdL[1024*240];
__device__ __align__(16) float g_bsE[896], g_bsD[1024];

__device__ __forceinline__ float sigm(float x){ return 1.0f/(1.0f+expf(-x)); }
// packed f32x2 FMA: bit-identical to scalar rn FMA
__device__ __forceinline__ void ffma4p(float4& a, const float4& x, const float4& w){
    unsigned long long* ap = reinterpret_cast<unsigned long long*>(&a);
    const unsigned long long* xp = reinterpret_cast<const unsigned long long*>(&x);
    const unsigned long long* wp = reinterpret_cast<const unsigned long long*>(&w);
    asm("fma.rn.f32x2 %0, %1, %2, %0;" : "+l"(ap[0]) : "l"(xp[0]), "l"(wp[0]));
    asm("fma.rn.f32x2 %0, %1, %2, %0;" : "+l"(ap[1]) : "l"(xp[1]), "l"(wp[1]));
}
__device__ __forceinline__ float hsum4(float4 a){ return a.x+a.y+a.z+a.w; }
__device__ __forceinline__ void splitpair(float x, float y, uint32_t& hi, uint32_t& lo){
    __nv_bfloat162 h = __floats2bfloat162_rn(x, y);
    __nv_bfloat162 l = __floats2bfloat162_rn(x - __bfloat162float(h.x), y - __bfloat162float(h.y));
    hi = *reinterpret_cast<uint32_t*>(&h);
    lo = *reinterpret_cast<uint32_t*>(&l);
}

// =====================  CONV STACK  =====================
__global__ __launch_bounds__(256) void conv1_k(const float* __restrict__ x,
        const float* __restrict__ cw, const float* __restrict__ cb, float* __restrict__ out){
    __shared__ float xin[66*30];
    __shared__ float w_s[36];
    __shared__ float b_s[4];
    int b = blockIdx.x/6, pho0 = (blockIdx.x%6)*32;
    int tid = threadIdx.x, lane = tid&31, warp = tid>>5;
    for(int f=tid; f<66*30; f+=256){
        int rr=f/30, cc=f%30;
        int gr=pho0*2-1+rr, gc=cc-1;
        float v=0.f;
        if(gr>=0 && gr<384 && gc>=0 && gc<28) v = x[((size_t)b*384+gr)*28+gc];
        xin[f]=v;
    }
    if(tid<36) w_s[tid]=cw[tid];
    if(tid<4)  b_s[tid]=cb[tid];
    __syncthreads();
    int wo = min(lane,27);
    for(int it=warp; it<128; it+=8){
        int oc=it>>5, ph=it&31;
        float wr[9];
        #pragma unroll
        for(int k=0;k<9;k++) wr[k]=w_s[oc*9+k];
        float bv=b_s[oc], s0=bv, s1=bv;
        #pragma unroll
        for(int kw=0;kw<3;kw++){
            float X[4];
            #pragma unroll
            for(int r=0;r<4;r++) X[r]=xin[(2*ph+r)*30+wo+kw];
            #pragma unroll
            for(int kh=0;kh<3;kh++){
                s0=fmaf(X[kh],  wr[kh*3+kw],s0);
                s1=fmaf(X[kh+1],wr[kh*3+kw],s1);
            }
        }
        float m = fmaxf(fmaxf(s0,0.f), fmaxf(s1,0.f));
        if(lane<28) out[((size_t)(b*4+oc)*192+pho0+ph)*28+wo]=m;
    }
}

// conv2: warp owns oc-quad {q,q+4,q+8,q+12}; X loads shared across 4 oc
__global__ __launch_bounds__(256) void conv2_k(const float* __restrict__ in,
        const float* __restrict__ cw, const float* __restrict__ cb, float* __restrict__ out){
    __shared__ float4 xin[34*30];
    __shared__ float4 w_s[144];
    __shared__ float  b_s[16];
    int b = blockIdx.x/6, pho0 = (blockIdx.x%6)*16;
    int tid = threadIdx.x, lane = tid&31, warp = tid>>5;
    for(int f=tid; f<34*30; f+=256){
        int rr=f/30, cc=f%30;
        int gr=pho0*2-1+rr, gc=cc-1;
        float4 v={0,0,0,0};
        if(gr>=0 && gr<192 && gc>=0 && gc<28){
            const float* p = in + ((size_t)b*4*192+gr)*28+gc;
            v.x=p[0]; v.y=p[192*28]; v.z=p[2*192*28]; v.w=p[3*192*28];
        }
        xin[f]=v;
    }
    for(int f=tid; f<144; f+=256){
        int oc=f/9, k=f%9;
        float4 v; v.x=cw[(oc*4+0)*9+k]; v.y=cw[(oc*4+1)*9+k];
                  v.z=cw[(oc*4+2)*9+k]; v.w=cw[(oc*4+3)*9+k];
        w_s[f]=v;
    }
    if(tid<16) b_s[tid]=cb[tid];
    __syncthreads();
    int wc = min(lane,27);
    int quad = warp&3;
    int pp0 = (warp>>2)*4;
    #pragma unroll 1
    for(int pi=0; pi<4; pi++){
        int pp = pp0 + pi;
        float4 a[4][4];
        #pragma unroll
        for(int o=0;o<4;o++)
            #pragma unroll
            for(int r=0;r<4;r++) a[o][r]=make_float4(0,0,0,0);
        #pragma unroll
        for(int kw=0;kw<3;kw++){
            float4 X[6];
            #pragma unroll
            for(int r=0;r<6;r++) X[r]=xin[(pp*4+r)*30+wc+kw];
            #pragma unroll
            for(int kh=0;kh<3;kh++){
                #pragma unroll
                for(int o=0;o<4;o++){
                    float4 w = w_s[(quad+4*o)*9+kh*3+kw];
                    ffma4p(a[o][0],X[kh],w); ffma4p(a[o][1],X[kh+1],w);
                    ffma4p(a[o][2],X[kh+2],w); ffma4p(a[o][3],X[kh+3],w);
                }
            }
        }
        #pragma unroll
        for(int o=0;o<4;o++){
            int oc = quad + 4*o;
            float bv = b_s[oc];
            float s0=hsum4(a[o][0])+bv, s1=hsum4(a[o][1])+bv;
            float s2=hsum4(a[o][2])+bv, s3=hsum4(a[o][3])+bv;
            float p0=fmaxf(fmaxf(s0,0.f),fmaxf(s1,0.f));
            float p1=fmaxf(fmaxf(s2,0.f),fmaxf(s3,0.f));
            float q0=fmaxf(p0, __shfl_down_sync(0xffffffffu,p0,1));
            float q1=fmaxf(p1, __shfl_down_sync(0xffffffffu,p1,1));
            if(!(lane&1) && lane<28){
                int wo=wc>>1;
                out[((size_t)(b*16+oc)*96+pho0+2*pp+0)*14+wo]=q0;
                out[((size_t)(b*16+oc)*96+pho0+2*pp+1)*14+wo]=q1;
            }
        }
    }
}

// conv3: half-warp owns oc-quad {q,q+4,q+8,q+12} x ph; X shared across 4 oc
__global__ __launch_bounds__(256) void conv3_k(const float* __restrict__ in,
        const float* __restrict__ cw, const float* __restrict__ cb, float* __restrict__ out){
    __shared__ float4 xin[4*26*16];
    __shared__ float4 w_s[576];
    __shared__ float  b_s[16];
    int b = blockIdx.x>>2, pho0 = (blockIdx.x&3)*8;
    int tid = threadIdx.x, lane = tid&31, warp = tid>>5;
    for(int f=tid; f<4*26*16; f+=256){
        int icg=f/(26*16), rr=(f/16)%26, cc=f%16;
        int gr=pho0*3-1+rr, gc=cc-1;
        float4 v={0,0,0,0};
        if(gr>=0 && gr<96 && gc>=0 && gc<14){
            const float* p = in + ((size_t)(b*16+icg*4)*96+gr)*14+gc;
            v.x=p[0]; v.y=p[96*14]; v.z=p[2*96*14]; v.w=p[3*96*14];
        }
        xin[f]=v;
    }
    for(int f=tid; f<576; f+=256){
        int oc=f/36, icg=(f/9)%4, k=f%9;
        float4 v;
        v.x=cw[(oc*16+icg*4+0)*9+k]; v.y=cw[(oc*16+icg*4+1)*9+k];
        v.z=cw[(oc*16+icg*4+2)*9+k]; v.w=cw[(oc*16+icg*4+3)*9+k];
        w_s[f]=v;
    }
    if(tid<16) b_s[tid]=cb[tid];
    __syncthreads();
    int half = lane>>4;
    int hw = warp*2 + half;           // 0..15
    int wc = min(lane&15, 13);
    int quad = hw&3;
    int ph0 = hw>>2;                  // 0..3
    #pragma unroll 1
    for(int i=0;i<2;i++){
        int ph = ph0 + 4*i;
        float4 acc[4][3];
        #pragma unroll
        for(int o=0;o<4;o++)
            #pragma unroll
            for(int r=0;r<3;r++) acc[o][r]=make_float4(0,0,0,0);
        #pragma unroll
        for(int icg=0;icg<4;icg++){
            #pragma unroll
            for(int kw=0;kw<3;kw++){
                float4 X[5];
                #pragma unroll
                for(int r=0;r<5;r++) X[r]=xin[(icg*26+3*ph+r)*16+wc+kw];
                #pragma unroll
                for(int kh=0;kh<3;kh++){
                    #pragma unroll
                    for(int o=0;o<4;o++){
                        float4 w = w_s[((quad+4*o)*4+icg)*9+kh*3+kw];
                        ffma4p(acc[o][0],X[kh],w);
                        ffma4p(acc[o][1],X[kh+1],w);
                        ffma4p(acc[o][2],X[kh+2],w);
                    }
                }
            }
        }
        #pragma unroll
        for(int o=0;o<4;o++){
            int oc = quad + 4*o;
            float bv = b_s[oc];
            float s0=fmaxf(hsum4(acc[o][0])+bv,0.f);
            float s1=fmaxf(hsum4(acc[o][1])+bv,0.f);
            float s2=fmaxf(hsum4(acc[o][2])+bv,0.f);
            float v=fmaxf(fmaxf(s0,s1),s2);
            float ov=fmaxf(v, __shfl_down_sync(0xffffffffu,v,1));
            if(!(lane&1) && (lane&15)<14)
                out[((size_t)(b*16+oc)*32+pho0+ph)*7+(wc>>1)]=ov;
        }
    }
}

// conv4: quarter-warp owns oc-quad {q,q+8,q+16,q+24} x hq; X shared across 4 oc
__global__ __launch_bounds__(256) void conv4_k(const float* __restrict__ in,
        const float* __restrict__ cw, const float* __restrict__ cb, float* __restrict__ out){
    __shared__ float4 xin[4*34*9];
    __shared__ float4 w_s[1152];
    __shared__ float  b_s[32];
    int b = blockIdx.x;
    int tid = threadIdx.x, lane = tid&31, warp = tid>>5;
    for(int f=tid; f<4*34*9; f+=256){
        int icg=f/(34*9), rr=(f/9)%34, cc=f%9;
        int gr=rr-1, gc=cc-1;
        float4 v={0,0,0,0};
        if(gr>=0 && gr<32 && gc>=0 && gc<7){
            const float* p = in + ((size_t)(b*16+icg*4)*32+gr)*7+gc;
            v.x=p[0]; v.y=p[32*7]; v.z=p[2*32*7]; v.w=p[3*32*7];
        }
        xin[f]=v;
    }
    for(int f=tid; f<1152; f+=256){
        int oc=f/36, icg=(f/9)%4, k=f%9;
        float4 v;
        v.x=cw[(oc*16+icg*4+0)*9+k]; v.y=cw[(oc*16+icg*4+1)*9+k];
        v.z=cw[(oc*16+icg*4+2)*9+k]; v.w=cw[(oc*16+icg*4+3)*9+k];
        w_s[f]=v;
    }
    if(tid<32) b_s[tid]=cb[tid];
    __syncthreads();
    int quarter = lane>>3;
    int qw = warp*4 + quarter;        // 0..31
    int wc = min(lane&7, 6);
    int quad = qw&7;
    int hq0 = qw>>3;                  // 0..3
    #pragma unroll 1
    for(int i=0;i<2;i++){
        int hq = hq0 + 4*i;
        float4 ac[4][4];
        #pragma unroll
        for(int o=0;o<4;o++)
            #pragma unroll
            for(int r=0;r<4;r++) ac[o][r]=make_float4(0,0,0,0);
        #pragma unroll
        for(int icg=0;icg<4;icg++){
            #pragma unroll
            for(int kw=0;kw<3;kw++){
                float4 X[6];
                #pragma unroll
                for(int r=0;r<6;r++) X[r]=xin[(icg*34+4*hq+r)*9+wc+kw];
                #pragma unroll
                for(int kh=0;kh<3;kh++){
                    #pragma unroll
                    for(int o=0;o<4;o++){
                        float4 w = w_s[((quad+8*o)*4+icg)*9+kh*3+kw];
                        #pragma unroll
                        for(int r=0;r<4;r++) ffma4p(ac[o][r],X[r+kh],w);
                    }
                }
            }
        }
        #pragma unroll
        for(int o=0;o<4;o++){
            int oc = quad + 8*o;
            float bv = b_s[oc];
            #pragma unroll
            for(int r=0;r<4;r++){
                float s=fmaxf(hsum4(ac[o][r])+bv,0.f);
                if((lane&7)<7)
                    out[((size_t)b*32+hq*4+r)*224+wc*32+oc]=s;
            }
        }
    }
}

// =====================  merged prep kernel  =====================
#define SEG0 100352            // 896*112
#define SEG1 (SEG0+100352)
#define SEG2 (SEG1+114688)     // 1024*112
#define SEG3 (SEG2+131072)     // 1024*128
#define SEG4 (SEG3+896)
#define SEG5 (SEG4+1024)
__global__ void prep_k(const float* __restrict__ lstmWih, const float* __restrict__ lstmWhh,
        const float* __restrict__ decWih, const float* __restrict__ decWhh,
        const float* __restrict__ lstmbih, const float* __restrict__ lstmbhh,
        const float* __restrict__ decbih, const float* __restrict__ decbhh){
    int idx = blockIdx.x*blockDim.x+threadIdx.x;
    if(idx >= SEG5) return;
    if(idx < SEG3){
        const float* W; uint32_t *Wh, *Wl;
        int base, kp2, kstride, gatesize;
        if(idx < SEG0){ W=lstmWih; Wh=g_WihH; Wl=g_WihL; base=0;    kp2=112; kstride=112; gatesize=224; }
        else if(idx < SEG1){ W=lstmWhh; Wh=g_WhhH; Wl=g_WhhL; base=SEG0; kp2=112; kstride=112; gatesize=224; }
        else if(idx < SEG2){ W=decWih;  Wh=g_WdH;  Wl=g_WdL;  base=SEG1; kp2=112; kstride=240; gatesize=256; }
        else { W=decWhh; Wh=g_WdH+112; Wl=g_WdL+112; base=SEG2; kp2=128; kstride=240; gatesize=256; }
        int li = idx - base;
        int kp = li%kp2, np = li/kp2;
        int Ksrc = kp2*2;
        int j=np>>2, gg=np&3;
        int srow = gg*gatesize+j;
        float x = W[(size_t)srow*Ksrc+2*kp], y = W[(size_t)srow*Ksrc+2*kp+1];
        uint32_t h,l; splitpair(x,y,h,l);
        Wh[(size_t)np*kstride+kp]=h; Wl[(size_t)np*kstride+kp]=l;
    } else if(idx < SEG4){
        int np = idx - SEG3;
        int j=np>>2, gg=np&3, s=gg*224+j;
        g_bsE[np] = lstmbih[s]+lstmbhh[s];
    } else {
        int np = idx - SEG4;
        int j=np>>2, gg=np&3, s=gg*256+j;
        g_bsD[np] = decbih[s]+decbhh[s];
    }
}

__global__ void split_a_k(const float* __restrict__ A, uint32_t* __restrict__ Ahi,
                          uint32_t* __restrict__ Alo, int total){
    int idx = blockIdx.x*blockDim.x+threadIdx.x;
    if(idx>=total) return;
    uint32_t h,l; splitpair(A[2*idx], A[2*idx+1], h, l);
    Ahi[idx]=h; Alo[idx]=l;
}
__global__ void init_enc_k(const float* __restrict__ h0, const float* __restrict__ c0){
    int idx = blockIdx.x*blockDim.x+threadIdx.x;
    if(idx < BSZ*AD) g_c[idx] = __ldg(c0 + idx%AD);
    if(idx < BSZ*112){
        int k = idx%112;
        uint32_t h,l; splitpair(__ldg(h0+2*k), __ldg(h0+2*k+1), h, l);
        g_Hh[idx]=h; g_Hl[idx]=l;
    }
}
__global__ void init_dec_k(){
    int idx = blockIdx.x*blockDim.x+threadIdx.x;
    if(idx>=BSZ*HID) return;
    g_dh[idx]=0.f; g_dc[idx]=0.f;
    int k = idx&255;
    if(k<128){ g_Ch[(idx>>8)*240+112+k]=0u; g_Cl[(idx>>8)*240+112+k]=0u; }
}
__global__ void enc_score_k(const float* __restrict__ att_w){
    int gl = blockIdx.x*blockDim.x+threadIdx.x;
    int row = gl>>5, lane = gl&31;
    if(row>=BSZ*TT) return;
    const float* r = g_y8 + (size_t)row*AD;
    const float* we = att_w + HID;
    float s=0.f;
    for(int k=lane;k<AD;k+=32) s += r[k]*__ldg(we+k);
    #pragma unroll
    for(int o=16;o>0;o>>=1) s += __shfl_xor_sync(0xffffffffu,s,o);
    if(lane==0) g_escore[row]=s;
}

// =====================  MMA core  =====================
#define MMA(c, a, b) asm volatile( \
    "mma.sync.aligned.m16n8k16.row.col.f32.bf16.bf16.f32 " \
    "{%0,%1,%2,%3},{%4,%5,%6,%7},{%8,%9},{%0,%1,%2,%3};" \
    : "+f"(c[0]),"+f"(c[1]),"+f"(c[2]),"+f"(c[3]) \
    : "r"(a[0]),"r"(a[1]),"r"(a[2]),"r"(a[3]),"r"(b[0]),"r"(b[1]))

__device__ __forceinline__ void mma_block(const uint32_t* __restrict__ Ah,
        const uint32_t* __restrict__ Al, const uint32_t* __restrict__ Bh,
        const uint32_t* __restrict__ Bl,
        float (&acc)[2][4][4], int wm, int wn, int g, int tg){
    #pragma unroll
    for(int kk=0;kk<2;kk++){
        uint32_t aH[2][4], aL[2][4], bH[4][2], bL[4][2];
        int kp = kk*8+tg;
        #pragma unroll
        for(int mi=0;mi<2;mi++){
            int r0 = wm*32+mi*16+g;
            aH[mi][0]=Ah[r0*17+kp];   aH[mi][1]=Ah[(r0+8)*17+kp];
            aH[mi][2]=Ah[r0*17+kp+4]; aH[mi][3]=Ah[(r0+8)*17+kp+4];
            aL[mi][0]=Al[r0*17+kp];   aL[mi][1]=Al[(r0+8)*17+kp];
            aL[mi][2]=Al[r0*17+kp+4]; aL[mi][3]=Al[(r0+8)*17+kp+4];
        }
        #pragma unroll
        for(int ni=0;ni<4;ni++){
            int c0 = wn*32+ni*8+g;
            bH[ni][0]=Bh[c0*17+kp]; bH[ni][1]=Bh[c0*17+kp+4];
            bL[ni][0]=Bl[c0*17+kp]; bL[ni][1]=Bl[c0*17+kp+4];
        }
        #pragma unroll
        for(int mi=0;mi<2;mi++)
            #pragma unroll
            for(int ni=0;ni<4;ni++){
                MMA(acc[mi][ni], aH[mi], bH[ni]);
                MMA(acc[mi][ni], aL[mi], bH[ni]);
                MMA(acc[mi][ni], aH[mi], bL[ni]);
            }
    }
}

// ---- double-buffered pipelined mainloop ----
#define BUFSZ (4*64*17)

__device__ __forceinline__ void ld8(uint4& a, uint4& b, const uint32_t* p){
    a = *(const uint4*)p; b = *(const uint4*)(p+4);
}
__device__ __forceinline__ void st8(uint32_t* d, uint4 a, uint4 b){
    d[0]=a.x; d[1]=a.y; d[2]=a.z; d[3]=a.w; d[4]=b.x; d[5]=b.y; d[6]=b.z; d[7]=b.w;
}

template<int NCHUNK>
__device__ __forceinline__ void gemm_pipe(
        const uint32_t* __restrict__ AsrcH, const uint32_t* __restrict__ AsrcL, int astr,
        const uint32_t* __restrict__ BsrcH, const uint32_t* __restrict__ BsrcL, int bstr,
        uint32_t* P, float (&acc)[2][4][4], int tid, int wm, int wn, int g, int tg){
    int lr = tid>>1, lkp = (tid&1)*8;
    const uint32_t* pah = AsrcH + (size_t)lr*astr + lkp;
    const uint32_t* pal = AsrcL + (size_t)lr*astr + lkp;
    const uint32_t* pbh = BsrcH + (size_t)lr*bstr + lkp;
    const uint32_t* pbl = BsrcL + (size_t)lr*bstr + lkp;
    uint4 ra0,ra1,rb0,rb1,rc0,rc1,rd0,rd1;
    ld8(ra0,ra1,pah); ld8(rb0,rb1,pal); ld8(rc0,rc1,pbh); ld8(rd0,rd1,pbl);
    int o = lr*17 + lkp;
    #pragma unroll
    for(int c=0;c<NCHUNK;c++){
        uint32_t* buf = P + (c&1)*BUFSZ;
        st8(buf+o, ra0,ra1);
        st8(buf+1088+o, rb0,rb1);
        st8(buf+2176+o, rc0,rc1);
        st8(buf+3264+o, rd0,rd1);
        __syncthreads();
        if(c+1<NCHUNK){
            ld8(ra0,ra1,pah + (c+1)*16); ld8(rb0,rb1,pal + (c+1)*16);
            ld8(rc0,rc1,pbh + (c+1)*16); ld8(rd0,rd1,pbl + (c+1)*16);
        }
        mma_block(buf, buf+1088, buf+2176, buf+3264, acc, wm, wn, g, tg);
    }
}

#define ACC_INIT(acc) { \
    _Pragma("unroll") for(int mi=0;mi<2;mi++) \
        _Pragma("unroll") for(int ni=0;ni<4;ni++) \
            _Pragma("unroll") for(int r=0;r<4;r++) acc[mi][ni][r]=0.f; }

#define ACC_TO_CS(acc, cs) { \
    _Pragma("unroll") for(int mi=0;mi<2;mi++){ \
        int r0 = wm*32+mi*16+g; \
        _Pragma("unroll") for(int ni=0;ni<4;ni++){ \
            int c0c = wn*32+ni*8+tg*2; \
            cs[r0*66+c0c]=acc[mi][ni][0];     cs[r0*66+c0c+1]=acc[mi][ni][1]; \
            cs[(r0+8)*66+c0c]=acc[mi][ni][2]; cs[(r0+8)*66+c0c+1]=acc[mi][ni][3]; \
        } } }

// =====================  xW GEMM (one-shot)  =====================
__global__ __launch_bounds__(128) void gemm_x(){
    __shared__ uint32_t P[2*BUFSZ];
    int tid=threadIdx.x;
    int m0=blockIdx.y*64, n0=blockIdx.x*64;
    int warp=tid>>5, lane=tid&31;
    int wm=warp>>1, wn=warp&1, g=lane>>2, tg=lane&3;
    float acc[2][4][4];
    ACC_INIT(acc);
    gemm_pipe<7>(g_Y5h + (size_t)m0*112, g_Y5l + (size_t)m0*112, 112,
                 g_WihH + (size_t)n0*112, g_WihL + (size_t)n0*112, 112,
                 P, acc, tid, wm, wn, g, tg);
    #pragma unroll
    for(int mi=0;mi<2;mi++){
        int row = m0+wm*32+mi*16+g;
        #pragma unroll
        for(int ni=0;ni<4;ni++){
            int col = n0+wn*32+ni*8+tg*2;
            float* p0 = g_xW + (size_t)row*896 + col;
            float* p1 = g_xW + (size_t)(row+8)*896 + col;
            p0[0]=acc[mi][ni][0]; p0[1]=acc[mi][ni][1];
            p1[0]=acc[mi][ni][2]; p1[1]=acc[mi][ni][3];
        }
    }
}

// =====================  encoder step (launch per t)  =====================
__global__ __launch_bounds__(128) void enc_step(int t){
    __shared__ uint32_t P[2*BUFSZ];
    float* cs = (float*)(P + BUFSZ);   // last mma (chunk 6) reads buffer 0
    int tid=threadIdx.x;
    int m0=blockIdx.y*64, n0=blockIdx.x*64;
    int warp=tid>>5, lane=tid&31;
    int wm=warp>>1, wn=warp&1, g=lane>>2, tg=lane&3;
    const uint32_t* srcH = g_Hh + (size_t)(t&1)*(BSZ*112);
    const uint32_t* srcL = g_Hl + (size_t)(t&1)*(BSZ*112);
    uint32_t* dstH = g_Hh + (size_t)((t+1)&1)*(BSZ*112);
    uint32_t* dstL = g_Hl + (size_t)((t+1)&1)*(BSZ*112);
    float acc[2][4][4];
    ACC_INIT(acc);
    gemm_pipe<7>(srcH + (size_t)m0*112, srcL + (size_t)m0*112, 112,
                 g_WhhH + (size_t)n0*112, g_WhhL + (size_t)n0*112, 112,
                 P, acc, tid, wm, wn, g, tg);
    ACC_TO_CS(acc, cs);
    __syncthreads();
    #pragma unroll 1
    for(int p=tid;p<512;p+=128){
        int m = p>>3, jp = p&7;
        int b = m0+m;
        const float* xw = g_xW + ((size_t)b*TT + t)*896 + n0 + 8*jp;
        float4 x0 = *(const float4*)xw;
        float4 x1 = *(const float4*)(xw+4);
        float4 s0 = *(const float4*)(g_bsE + n0 + 8*jp);
        float4 s1 = *(const float4*)(g_bsE + n0 + 8*jp + 4);
        const float* cp = cs + m*66 + 8*jp;
        float gi0=cp[0]+x0.x+s0.x, gf0=cp[1]+x0.y+s0.y, gg0=cp[2]+x0.z+s0.z, go0=cp[3]+x0.w+s0.w;
        float gi1=cp[4]+x1.x+s1.x, gf1=cp[5]+x1.y+s1.y, gg1=cp[6]+x1.z+s1.z, go1=cp[7]+x1.w+s1.w;
        int j0 = (n0>>2) + 2*jp;
        float c0v = g_c[(size_t)b*AD + j0];
        float c1v = g_c[(size_t)b*AD + j0 + 1];
        float cc0 = sigm(gf0)*c0v + sigm(gi0)*tanhf(gg0);
        float cc1 = sigm(gf1)*c1v + sigm(gi1)*tanhf(gg1);
        float h0v = sigm(go0)*tanhf(cc0);
        float h1v = sigm(go1)*tanhf(cc1);
        g_c[(size_t)b*AD + j0]   = cc0;
        g_c[(size_t)b*AD + j0+1] = cc1;
        float* yp = g_y8 + ((size_t)b*TT + t)*AD + j0;
        yp[0]=h0v; yp[1]=h1v;
        uint32_t hh,ll; splitpair(h0v,h1v,hh,ll);
        dstH[(size_t)b*112 + (n0>>3) + jp] = hh;
        dstL[(size_t)b*112 + (n0>>3) + jp] = ll;
    }
}

// =====================  decoder step GEMM+cell (launch per s)  =====================
__global__ __launch_bounds__(128) void dec_step(int s){
    __shared__ uint32_t P[2*BUFSZ];
    float* cs = (float*)(P + BUFSZ);   // last mma (chunk 14) reads buffer 0
    int tid=threadIdx.x;
    int m0=blockIdx.y*64, n0=blockIdx.x*64;
    int warp=tid>>5, lane=tid&31;
    int wm=warp>>1, wn=warp&1, g=lane>>2, tg=lane&3;
    const uint32_t* srcH = g_Ch + (size_t)(s&1)*(BSZ*240);
    const uint32_t* srcL = g_Cl + (size_t)(s&1)*(BSZ*240);
    uint32_t* dstH = g_Ch + (size_t)((s+1)&1)*(BSZ*240);
    uint32_t* dstL = g_Cl + (size_t)((s+1)&1)*(BSZ*240);
    float acc[2][4][4];
    ACC_INIT(acc);
    gemm_pipe<15>(srcH + (size_t)m0*240, srcL + (size_t)m0*240, 240,
                  g_WdH + (size_t)n0*240, g_WdL + (size_t)n0*240, 240,
                  P, acc, tid, wm, wn, g, tg);
    ACC_TO_CS(acc, cs);
    __syncthreads();
    #pragma unroll 1
    for(int p=tid;p<512;p+=128){
        int m = p>>3, jp = p&7;
        int b = m0+m;
        float4 s0 = *(const float4*)(g_bsD + n0 + 8*jp);
        float4 s1 = *(const float4*)(g_bsD + n0 + 8*jp + 4);
        const float* cp = cs + m*66 + 8*jp;
        float gi0=cp[0]+s0.x, gf0=cp[1]+s0.y, gg0=cp[2]+s0.z, go0=cp[3]+s0.w;
        float gi1=cp[4]+s1.x, gf1=cp[5]+s1.y, gg1=cp[6]+s1.z, go1=cp[7]+s1.w;
        int j0 = (n0>>2) + 2*jp;
        float c0v = g_dc[(size_t)b*HID + j0];
        float c1v = g_dc[(size_t)b*HID + j0 + 1];
        float cc0 = sigm(gf0)*c0v + sigm(gi0)*tanhf(gg0);
        float cc1 = sigm(gf1)*c1v + sigm(gi1)*tanhf(gg1);
        float h0v = sigm(go0)*tanhf(cc0);
        float h1v = sigm(go1)*tanhf(cc1);
        g_dc[(size_t)b*HID + j0]   = cc0;
        g_dc[(size_t)b*HID + j0+1] = cc1;
        g_dh[(size_t)b*HID + j0]   = h0v;
        g_dh[(size_t)b*HID + j0+1] = h1v;
        uint32_t hh,ll; splitpair(h0v,h1v,hh,ll);
        dstH[(size_t)b*240 + 112 + (n0>>3) + jp] = hh;
        dstL[(size_t)b*240 + 112 + (n0>>3) + jp] = ll;
    }
}

// =====================  fused attention + output projection  =====================
__global__ __launch_bounds__(256) void attn_out_k(const float* __restrict__ attw,
        const float* __restrict__ attb, const float* __restrict__ outw,
        const float* __restrict__ outb, float* __restrict__ out, int s){
    int b = blockIdx.x, tid = threadIdx.x;
    __shared__ float dh_s[256];
    __shared__ float red[256];
    __shared__ float sc[TT];
    __shared__ float ctx_s[AD];
    dh_s[tid] = g_dh[(size_t)b*HID + tid];
    __syncthreads();

    if(s < OUT_LEN){
        red[tid] = dh_s[tid]*__ldg(attw+tid);
        __syncthreads();
        #pragma unroll
        for(int r=128;r>0;r>>=1){ if(tid<r) red[tid]+=red[tid+r]; __syncthreads(); }
        float hw = red[0] + __ldg(attb);
        if(tid < 32){
            float x = g_escore[b*TT + tid] + hw;
            float mx = x;
            #pragma unroll
            for(int o=16;o>0;o>>=1) mx = fmaxf(mx,__shfl_xor_sync(0xffffffffu,mx,o));
            float e = expf(x-mx), sm = e;
            #pragma unroll
            for(int o=16;o>0;o>>=1) sm += __shfl_xor_sync(0xffffffffu,sm,o);
            sc[tid] = e/sm;
        }
        __syncthreads();
        if(tid < AD){
            const float* y = g_y8 + (size_t)b*TT*AD + tid;
            float acc=0.f;
            #pragma unroll
            for(int t=0;t<TT;t++) acc = fmaf(sc[t], y[t*AD], acc);
            ctx_s[tid]=acc;
        }
        __syncthreads();
        if(tid < 112){
            uint32_t hh,ll; splitpair(ctx_s[2*tid], ctx_s[2*tid+1], hh, ll);
            g_Ch[(size_t)(s&1)*(BSZ*240) + (size_t)b*240 + tid] = hh;
            g_Cl[(size_t)(s&1)*(BSZ*240) + (size_t)b*240 + tid] = ll;
        }
    }
    if(s > 0){
        int w = tid>>5, lane = tid&31;
        #pragma unroll
        for(int v=w; v<VOCAB; v+=8){
            const float* wp = outw + (size_t)v*HID;
            float sum = 0.f;
            #pragma unroll
            for(int q=0;q<8;q++) sum = fmaf(dh_s[lane+32*q], __ldg(wp+lane+32*q), sum);
            #pragma unroll
            for(int o=16;o>0;o>>=1) sum += __shfl_xor_sync(0xffffffffu,sum,o);
            if(lane==0)
                out[(size_t)b*VOCAB*OUT_LEN + v*OUT_LEN + (s-1)] = sum + __ldg(outb+v);
        }
    }
}

// =====================  launch  =====================
extern "C" void kernel_launch(void* const* d_in, const int* in_sizes, int n_in,
                              void* d_out, int out_size){
    const float* x       = (const float*)d_in[0];
    const float* c1w     = (const float*)d_in[1];
    const float* c1b     = (const float*)d_in[2];
    const float* c2w     = (const float*)d_in[3];
    const float* c2b     = (const float*)d_in[4];
    const float* c3w     = (const float*)d_in[5];
    const float* c3b     = (const float*)d_in[6];
    const float* c4w     = (const float*)d_in[7];
    const float* c4b     = (const float*)d_in[8];
    const float* h0      = (const float*)d_in[9];
    const float* c0      = (const float*)d_in[10];
    const float* lstmWih = (const float*)d_in[11];
    const float* lstmWhh = (const float*)d_in[12];
    const float* lstmbih = (const float*)d_in[13];
    const float* lstmbhh = (const float*)d_in[14];
    const float* attw    = (const float*)d_in[15];
    const float* attb    = (const float*)d_in[16];
    const float* decWih  = (const float*)d_in[17];
    const float* decWhh  = (const float*)d_in[18];
    const float* decbih  = (const float*)d_in[19];
    const float* decbhh  = (const float*)d_in[20];
    const float* outw    = (const float*)d_in[21];
    const float* outb    = (const float*)d_in[22];
    float* out = (float*)d_out;

    float *y1,*y2,*y3,*y5;
    uint32_t *Y5h,*Y5l;
    cudaGetSymbolAddress((void**)&y1,  g_y1);
    cudaGetSymbolAddress((void**)&y2,  g_y2);
    cudaGetSymbolAddress((void**)&y3,  g_y3);
    cudaGetSymbolAddress((void**)&y5,  g_y5);
    cudaGetSymbolAddress((void**)&Y5h, g_Y5h);
    cudaGetSymbolAddress((void**)&Y5l, g_Y5l);

    // merged weight prep (1 launch)
    prep_k<<<(SEG5+255)/256,256>>>(lstmWih, lstmWhh, decWih, decWhh,
                                   lstmbih, lstmbhh, decbih, decbhh);

    // conv stack
    conv1_k<<<BSZ*6,256>>>(x,  c1w, c1b, y1);
    conv2_k<<<BSZ*6,256>>>(y1, c2w, c2b, y2);
    conv3_k<<<BSZ*4,256>>>(y2, c3w, c3b, y3);
    conv4_k<<<BSZ,  256>>>(y3, c4w, c4b, y5);

    // split y5 then xW GEMM
    split_a_k<<<(BSZ*TT*112+255)/256,256>>>(y5, Y5h, Y5l, BSZ*TT*112);
    gemm_x<<<dim3(14,512),128>>>();

    // encoder scan
    init_enc_k<<<(BSZ*AD+255)/256,256>>>(h0, c0);
    for(int t=0;t<TT;t++)
        enc_step<<<dim3(14,16),128>>>(t);

    // attention precompute + decoder init
    enc_score_k<<<(BSZ*TT*32+255)/256,256>>>(attw);
    init_dec_k<<<(BSZ*HID+255)/256,256>>>();

    // decoder scan: attn(s)+out(s-1), then gemm+cell(s); final launch emits out(24)
    for(int s=0;s<=OUT_LEN;s++){
        attn_out_k<<<BSZ,256>>>(attw, attb, outw, outb, out, s);
        if(s<OUT_LEN) dec_step<<<dim3(16,16),128>>>(s);
    }
}

// round 12
// speedup vs baseline: 1.3165x; 1.3165x over previous
#include <cuda_runtime.h>
#include <cuda_bf16.h>
#include <cstdint>

#define BSZ  1024
#define TT   32
#define AD   224
#define HID  256
#define VOCAB 29
#define OUT_LEN 25

// ---------------- scratch (device globals) ----------------
__device__ float g_y1[BSZ*4*192*28];
__device__ float g_y2[BSZ*16*96*14];
__device__ float g_y3[BSZ*16*32*7];
__device__ float g_y5[BSZ*TT*AD];
__device__ __align__(16) float g_xW[BSZ*TT*896];
__device__ __align__(16) float g_y8[BSZ*TT*AD];
__device__ float g_escore[BSZ*TT];
__device__ float g_c [BSZ*AD];
__device__ float g_dh[BSZ*HID];
__device__ float g_dc[BSZ*HID];
// pre-split activations (bf16 hi/lo pairs packed as u32)
__device__ __align__(16) uint32_t g_Y5h[BSZ*TT*112], g_Y5l[BSZ*TT*112];
__device__ __align__(16) uint32_t g_Hh[2*BSZ*112],   g_Hl[2*BSZ*112];
__device__ __align__(16) uint32_t g_Ch[2*BSZ*240],   g_Cl[2*BSZ*240];
// pre-split weights, gate-interleaved rows
__device__ __align__(16) uint32_t g_WihH[896*112], g_WihL[896*112];
__device__ __align__(16) uint32_t g_WhhH[896*112], g_WhhL[896*112];
__device__ __align__(16) uint32_t g_WdH[1024*240], g_WdL[1024*240];
__device__ __align__(16) float g_bsE[896], g_bsD[1024];

__device__ __forceinline__ float sigm(float x){ return 1.0f/(1.0f+expf(-x)); }
// packed f32x2 FMA: bit-identical to scalar rn FMA
__device__ __forceinline__ void ffma4p(float4& a, const float4& x, const float4& w){
    unsigned long long* ap = reinterpret_cast<unsigned long long*>(&a);
    const unsigned long long* xp = reinterpret_cast<const unsigned long long*>(&x);
    const unsigned long long* wp = reinterpret_cast<const unsigned long long*>(&w);
    asm("fma.rn.f32x2 %0, %1, %2, %0;" : "+l"(ap[0]) : "l"(xp[0]), "l"(wp[0]));
    asm("fma.rn.f32x2 %0, %1, %2, %0;" : "+l"(ap[1]) : "l"(xp[1]), "l"(wp[1]));
}
__device__ __forceinline__ float hsum4(float4 a){ return a.x+a.y+a.z+a.w; }
__device__ __forceinline__ void splitpair(float x, float y, uint32_t& hi, uint32_t& lo){
    __nv_bfloat162 h = __floats2bfloat162_rn(x, y);
    __nv_bfloat162 l = __floats2bfloat162_rn(x - __bfloat162float(h.x), y - __bfloat162float(h.y));
    hi = *reinterpret_cast<uint32_t*>(&h);
    lo = *reinterpret_cast<uint32_t*>(&l);
}

// =====================  CONV STACK (exact R10 versions)  =====================
__global__ __launch_bounds__(256) void conv1_k(const float* __restrict__ x,
        const float* __restrict__ cw, const float* __restrict__ cb, float* __restrict__ out){
    __shared__ float xin[66*30];
    __shared__ float w_s[36];
    __shared__ float b_s[4];
    int b = blockIdx.x/6, pho0 = (blockIdx.x%6)*32;
    int tid = threadIdx.x, lane = tid&31, warp = tid>>5;
    for(int f=tid; f<66*30; f+=256){
        int rr=f/30, cc=f%30;
        int gr=pho0*2-1+rr, gc=cc-1;
        float v=0.f;
        if(gr>=0 && gr<384 && gc>=0 && gc<28) v = x[((size_t)b*384+gr)*28+gc];
        xin[f]=v;
    }
    if(tid<36) w_s[tid]=cw[tid];
    if(tid<4)  b_s[tid]=cb[tid];
    __syncthreads();
    int wo = min(lane,27);
    for(int it=warp; it<128; it+=8){
        int oc=it>>5, ph=it&31;
        float wr[9];
        #pragma unroll
        for(int k=0;k<9;k++) wr[k]=w_s[oc*9+k];
        float bv=b_s[oc], s0=bv, s1=bv;
        #pragma unroll
        for(int kw=0;kw<3;kw++){
            float X[4];
            #pragma unroll
            for(int r=0;r<4;r++) X[r]=xin[(2*ph+r)*30+wo+kw];
            #pragma unroll
            for(int kh=0;kh<3;kh++){
                s0=fmaf(X[kh],  wr[kh*3+kw],s0);
                s1=fmaf(X[kh+1],wr[kh*3+kw],s1);
            }
        }
        float m = fmaxf(fmaxf(s0,0.f), fmaxf(s1,0.f));
        if(lane<28) out[((size_t)(b*4+oc)*192+pho0+ph)*28+wo]=m;
    }
}

// conv2: warp owns oc-pair {p, p+8}; X loads shared across both oc
__global__ __launch_bounds__(256) void conv2_k(const float* __restrict__ in,
        const float* __restrict__ cw, const float* __restrict__ cb, float* __restrict__ out){
    __shared__ float4 xin[34*30];
    __shared__ float4 w_s[144];
    __shared__ float  b_s[16];
    int b = blockIdx.x/6, pho0 = (blockIdx.x%6)*16;
    int tid = threadIdx.x, lane = tid&31, warp = tid>>5;
    for(int f=tid; f<34*30; f+=256){
        int rr=f/30, cc=f%30;
        int gr=pho0*2-1+rr, gc=cc-1;
        float4 v={0,0,0,0};
        if(gr>=0 && gr<192 && gc>=0 && gc<28){
            const float* p = in + ((size_t)b*4*192+gr)*28+gc;
            v.x=p[0]; v.y=p[192*28]; v.z=p[2*192*28]; v.w=p[3*192*28];
        }
        xin[f]=v;
    }
    for(int f=tid; f<144; f+=256){
        int oc=f/9, k=f%9;
        float4 v; v.x=cw[(oc*4+0)*9+k]; v.y=cw[(oc*4+1)*9+k];
                  v.z=cw[(oc*4+2)*9+k]; v.w=cw[(oc*4+3)*9+k];
        w_s[f]=v;
    }
    if(tid<16) b_s[tid]=cb[tid];
    __syncthreads();
    int wc = min(lane,27);
    int oc0 = warp, oc1 = warp+8;
    float bv0 = b_s[oc0], bv1 = b_s[oc1];
    #pragma unroll 1
    for(int pp=0; pp<8; pp++){
        float4 a[2][4];
        #pragma unroll
        for(int o=0;o<2;o++)
            #pragma unroll
            for(int r=0;r<4;r++) a[o][r]=make_float4(0,0,0,0);
        #pragma unroll
        for(int kw=0;kw<3;kw++){
            float4 X[6];
            #pragma unroll
            for(int r=0;r<6;r++) X[r]=xin[(pp*4+r)*30+wc+kw];
            #pragma unroll
            for(int kh=0;kh<3;kh++){
                float4 w0=w_s[oc0*9+kh*3+kw];
                float4 w1=w_s[oc1*9+kh*3+kw];
                ffma4p(a[0][0],X[kh],w0); ffma4p(a[0][1],X[kh+1],w0);
                ffma4p(a[0][2],X[kh+2],w0); ffma4p(a[0][3],X[kh+3],w0);
                ffma4p(a[1][0],X[kh],w1); ffma4p(a[1][1],X[kh+1],w1);
                ffma4p(a[1][2],X[kh+2],w1); ffma4p(a[1][3],X[kh+3],w1);
            }
        }
        #pragma unroll
        for(int o=0;o<2;o++){
            int oc = o ? oc1 : oc0;
            float bv = o ? bv1 : bv0;
            float s0=hsum4(a[o][0])+bv, s1=hsum4(a[o][1])+bv;
            float s2=hsum4(a[o][2])+bv, s3=hsum4(a[o][3])+bv;
            float p0=fmaxf(fmaxf(s0,0.f),fmaxf(s1,0.f));
            float p1=fmaxf(fmaxf(s2,0.f),fmaxf(s3,0.f));
            float q0=fmaxf(p0, __shfl_down_sync(0xffffffffu,p0,1));
            float q1=fmaxf(p1, __shfl_down_sync(0xffffffffu,p1,1));
            if(!(lane&1) && lane<28){
                int wo=wc>>1;
                out[((size_t)(b*16+oc)*96+pho0+2*pp+0)*14+wo]=q0;
                out[((size_t)(b*16+oc)*96+pho0+2*pp+1)*14+wo]=q1;
            }
        }
    }
}

// conv3: half-warp owns oc-pair {p, p+8} per item; X shared across both oc
__global__ __launch_bounds__(256) void conv3_k(const float* __restrict__ in,
        const float* __restrict__ cw, const float* __restrict__ cb, float* __restrict__ out){
    __shared__ float4 xin[4*26*16];
    __shared__ float4 w_s[576];
    __shared__ float  b_s[16];
    int b = blockIdx.x>>2, pho0 = (blockIdx.x&3)*8;
    int tid = threadIdx.x, lane = tid&31, warp = tid>>5;
    for(int f=tid; f<4*26*16; f+=256){
        int icg=f/(26*16), rr=(f/16)%26, cc=f%16;
        int gr=pho0*3-1+rr, gc=cc-1;
        float4 v={0,0,0,0};
        if(gr>=0 && gr<96 && gc>=0 && gc<14){
            const float* p = in + ((size_t)(b*16+icg*4)*96+gr)*14+gc;
            v.x=p[0]; v.y=p[96*14]; v.z=p[2*96*14]; v.w=p[3*96*14];
        }
        xin[f]=v;
    }
    for(int f=tid; f<576; f+=256){
        int oc=f/36, icg=(f/9)%4, k=f%9;
        float4 v;
        v.x=cw[(oc*16+icg*4+0)*9+k]; v.y=cw[(oc*16+icg*4+1)*9+k];
        v.z=cw[(oc*16+icg*4+2)*9+k]; v.w=cw[(oc*16+icg*4+3)*9+k];
        w_s[f]=v;
    }
    if(tid<16) b_s[tid]=cb[tid];
    __syncthreads();
    int half = lane>>4;
    int hw = warp*2 + half;           // 0..15
    int wc = min(lane&15, 13);
    #pragma unroll 1
    for(int it=hw; it<64; it+=16){
        int pair = it>>3, ph = it&7;
        int oc0 = pair, oc1 = pair+8;
        float4 acc[2][3];
        #pragma unroll
        for(int o=0;o<2;o++)
            #pragma unroll
            for(int r=0;r<3;r++) acc[o][r]=make_float4(0,0,0,0);
        #pragma unroll
        for(int icg=0;icg<4;icg++){
            #pragma unroll
            for(int kw=0;kw<3;kw++){
                float4 X[5];
                #pragma unroll
                for(int r=0;r<5;r++) X[r]=xin[(icg*26+3*ph+r)*16+wc+kw];
                #pragma unroll
                for(int kh=0;kh<3;kh++){
                    float4 w0=w_s[(oc0*4+icg)*9+kh*3+kw];
                    float4 w1=w_s[(oc1*4+icg)*9+kh*3+kw];
                    ffma4p(acc[0][0],X[kh],w0);
                    ffma4p(acc[0][1],X[kh+1],w0);
                    ffma4p(acc[0][2],X[kh+2],w0);
                    ffma4p(acc[1][0],X[kh],w1);
                    ffma4p(acc[1][1],X[kh+1],w1);
                    ffma4p(acc[1][2],X[kh+2],w1);
                }
            }
        }
        #pragma unroll
        for(int o=0;o<2;o++){
            int oc = o ? oc1 : oc0;
            float bv = b_s[oc];
            float s0=fmaxf(hsum4(acc[o][0])+bv,0.f);
            float s1=fmaxf(hsum4(acc[o][1])+bv,0.f);
            float s2=fmaxf(hsum4(acc[o][2])+bv,0.f);
            float v=fmaxf(fmaxf(s0,s1),s2);
            float ov=fmaxf(v, __shfl_down_sync(0xffffffffu,v,1));
            if(!(lane&1) && (lane&15)<14)
                out[((size_t)(b*16+oc)*32+pho0+ph)*7+(wc>>1)]=ov;
        }
    }
}

// conv4: quarter-warp owns oc-pair {p, p+16} per item; X shared across both oc
__global__ __launch_bounds__(256) void conv4_k(const float* __restrict__ in,
        const float* __restrict__ cw, const float* __restrict__ cb, float* __restrict__ out){
    __shared__ float4 xin[4*34*9];
    __shared__ float4 w_s[1152];
    __shared__ float  b_s[32];
    int b = blockIdx.x;
    int tid = threadIdx.x, lane = tid&31, warp = tid>>5;
    for(int f=tid; f<4*34*9; f+=256){
        int icg=f/(34*9), rr=(f/9)%34, cc=f%9;
        int gr=rr-1, gc=cc-1;
        float4 v={0,0,0,0};
        if(gr>=0 && gr<32 && gc>=0 && gc<7){
            const float* p = in + ((size_t)(b*16+icg*4)*32+gr)*7+gc;
            v.x=p[0]; v.y=p[32*7]; v.z=p[2*32*7]; v.w=p[3*32*7];
        }
        xin[f]=v;
    }
    for(int f=tid; f<1152; f+=256){
        int oc=f/36, icg=(f/9)%4, k=f%9;
        float4 v;
        v.x=cw[(oc*16+icg*4+0)*9+k]; v.y=cw[(oc*16+icg*4+1)*9+k];
        v.z=cw[(oc*16+icg*4+2)*9+k]; v.w=cw[(oc*16+icg*4+3)*9+k];
        w_s[f]=v;
    }
    if(tid<32) b_s[tid]=cb[tid];
    __syncthreads();
    int quarter = lane>>3;
    int qw = warp*4 + quarter;        // 0..31
    int wc = min(lane&7, 6);
    #pragma unroll 1
    for(int it=qw; it<128; it+=32){
        int pair = it>>3, hq = it&7;
        int oc0 = pair, oc1 = pair+16;
        float4 ac[2][4];
        #pragma unroll
        for(int o=0;o<2;o++)
            #pragma unroll
            for(int r=0;r<4;r++) ac[o][r]=make_float4(0,0,0,0);
        #pragma unroll
        for(int icg=0;icg<4;icg++){
            #pragma unroll
            for(int kw=0;kw<3;kw++){
                float4 X[6];
                #pragma unroll
                for(int r=0;r<6;r++) X[r]=xin[(icg*34+4*hq+r)*9+wc+kw];
                #pragma unroll
                for(int kh=0;kh<3;kh++){
                    float4 w0=w_s[(oc0*4+icg)*9+kh*3+kw];
                    float4 w1=w_s[(oc1*4+icg)*9+kh*3+kw];
                    #pragma unroll
                    for(int r=0;r<4;r++) ffma4p(ac[0][r],X[r+kh],w0);
                    #pragma unroll
                    for(int r=0;r<4;r++) ffma4p(ac[1][r],X[r+kh],w1);
                }
            }
        }
        #pragma unroll
        for(int o=0;o<2;o++){
            int oc = o ? oc1 : oc0;
            float bv = b_s[oc];
            #pragma unroll
            for(int r=0;r<4;r++){
                float s=fmaxf(hsum4(ac[o][r])+bv,0.f);
                if((lane&7)<7)
                    out[((size_t)b*32+hq*4+r)*224+wc*32+oc]=s;
            }
        }
    }
}

// =====================  merged prep kernel  =====================
#define SEG0 100352            // 896*112
#define SEG1 (SEG0+100352)
#define SEG2 (SEG1+114688)     // 1024*112
#define SEG3 (SEG2+131072)     // 1024*128
#define SEG4 (SEG3+896)
#define SEG5 (SEG4+1024)
__global__ void prep_k(const float* __restrict__ lstmWih, const float* __restrict__ lstmWhh,
        const float* __restrict__ decWih, const float* __restrict__ decWhh,
        const float* __restrict__ lstmbih, const float* __restrict__ lstmbhh,
        const float* __restrict__ decbih, const float* __restrict__ decbhh){
    int idx = blockIdx.x*blockDim.x+threadIdx.x;
    if(idx >= SEG5) return;
    if(idx < SEG3){
        const float* W; uint32_t *Wh, *Wl;
        int base, kp2, kstride, gatesize;
        if(idx < SEG0){ W=lstmWih; Wh=g_WihH; Wl=g_WihL; base=0;    kp2=112; kstride=112; gatesize=224; }
        else if(idx < SEG1){ W=lstmWhh; Wh=g_WhhH; Wl=g_WhhL; base=SEG0; kp2=112; kstride=112; gatesize=224; }
        else if(idx < SEG2){ W=decWih;  Wh=g_WdH;  Wl=g_WdL;  base=SEG1; kp2=112; kstride=240; gatesize=256; }
        else { W=decWhh; Wh=g_WdH+112; Wl=g_WdL+112; base=SEG2; kp2=128; kstride=240; gatesize=256; }
        int li = idx - base;
        int kp = li%kp2, np = li/kp2;
        int Ksrc = kp2*2;
        int j=np>>2, gg=np&3;
        int srow = gg*gatesize+j;
        float x = W[(size_t)srow*Ksrc+2*kp], y = W[(size_t)srow*Ksrc+2*kp+1];
        uint32_t h,l; splitpair(x,y,h,l);
        Wh[(size_t)np*kstride+kp]=h; Wl[(size_t)np*kstride+kp]=l;
    } else if(idx < SEG4){
        int np = idx - SEG3;
        int j=np>>2, gg=np&3, s=gg*224+j;
        g_bsE[np] = lstmbih[s]+lstmbhh[s];
    } else {
        int np = idx - SEG4;
        int j=np>>2, gg=np&3, s=gg*256+j;
        g_bsD[np] = decbih[s]+decbhh[s];
    }
}

__global__ void split_a_k(const float* __restrict__ A, uint32_t* __restrict__ Ahi,
                          uint32_t* __restrict__ Alo, int total){
    int idx = blockIdx.x*blockDim.x+threadIdx.x;
    if(idx>=total) return;
    uint32_t h,l; splitpair(A[2*idx], A[2*idx+1], h, l);
    Ahi[idx]=h; Alo[idx]=l;
}
__global__ void init_enc_k(const float* __restrict__ h0, const float* __restrict__ c0){
    int idx = blockIdx.x*blockDim.x+threadIdx.x;
    if(idx < BSZ*AD) g_c[idx] = __ldg(c0 + idx%AD);
    if(idx < BSZ*112){
        int k = idx%112;
        uint32_t h,l; splitpair(__ldg(h0+2*k), __ldg(h0+2*k+1), h, l);
        g_Hh[idx]=h; g_Hl[idx]=l;
    }
}
__global__ void init_dec_k(){
    int idx = blockIdx.x*blockDim.x+threadIdx.x;
    if(idx>=BSZ*HID) return;
    g_dh[idx]=0.f; g_dc[idx]=0.f;
    int k = idx&255;
    if(k<128){ g_Ch[(idx>>8)*240+112+k]=0u; g_Cl[(idx>>8)*240+112+k]=0u; }
}
__global__ void enc_score_k(const float* __restrict__ att_w){
    int gl = blockIdx.x*blockDim.x+threadIdx.x;
    int row = gl>>5, lane = gl&31;
    if(row>=BSZ*TT) return;
    const float* r = g_y8 + (size_t)row*AD;
    const float* we = att_w + HID;
    float s=0.f;
    for(int k=lane;k<AD;k+=32) s += r[k]*__ldg(we+k);
    #pragma unroll
    for(int o=16;o>0;o>>=1) s += __shfl_xor_sync(0xffffffffu,s,o);
    if(lane==0) g_escore[row]=s;
}

// =====================  MMA core (256-thread blocks, 8 warps, 64x64 tile)  =====================
#define MMA(c, a, b) asm volatile( \
    "mma.sync.aligned.m16n8k16.row.col.f32.bf16.bf16.f32 " \
    "{%0,%1,%2,%3},{%4,%5,%6,%7},{%8,%9},{%0,%1,%2,%3};" \
    : "+f"(c[0]),"+f"(c[1]),"+f"(c[2]),"+f"(c[3]) \
    : "r"(a[0]),"r"(a[1]),"r"(a[2]),"r"(a[3]),"r"(b[0]),"r"(b[1]))

// warp grid 2x4: each warp computes 32 rows x 16 cols (mi=2, ni=2)
__device__ __forceinline__ void mma_block(const uint32_t* __restrict__ Ah,
        const uint32_t* __restrict__ Al, const uint32_t* __restrict__ Bh,
        const uint32_t* __restrict__ Bl,
        float (&acc)[2][2][4], int wm, int wn, int g, int tg){
    #pragma unroll
    for(int kk=0;kk<2;kk++){
        uint32_t aH[2][4], aL[2][4], bH[2][2], bL[2][2];
        int kp = kk*8+tg;
        #pragma unroll
        for(int mi=0;mi<2;mi++){
            int r0 = wm*32+mi*16+g;
            aH[mi][0]=Ah[r0*17+kp];   aH[mi][1]=Ah[(r0+8)*17+kp];
            aH[mi][2]=Ah[r0*17+kp+4]; aH[mi][3]=Ah[(r0+8)*17+kp+4];
            aL[mi][0]=Al[r0*17+kp];   aL[mi][1]=Al[(r0+8)*17+kp];
            aL[mi][2]=Al[r0*17+kp+4]; aL[mi][3]=Al[(r0+8)*17+kp+4];
        }
        #pragma unroll
        for(int ni=0;ni<2;ni++){
            int c0 = wn*16+ni*8+g;
            bH[ni][0]=Bh[c0*17+kp]; bH[ni][1]=Bh[c0*17+kp+4];
            bL[ni][0]=Bl[c0*17+kp]; bL[ni][1]=Bl[c0*17+kp+4];
        }
        #pragma unroll
        for(int mi=0;mi<2;mi++)
            #pragma unroll
            for(int ni=0;ni<2;ni++){
                MMA(acc[mi][ni], aH[mi], bH[ni]);
                MMA(acc[mi][ni], aL[mi], bH[ni]);
                MMA(acc[mi][ni], aH[mi], bL[ni]);
            }
    }
}

// ---- double-buffered pipelined mainloop (256 threads: 1 uint4/array/thread) ----
#define BUFSZ (4*64*17)

template<int NCHUNK>
__device__ __forceinline__ void gemm_pipe(
        const uint32_t* __restrict__ AsrcH, const uint32_t* __restrict__ AsrcL, int astr,
        const uint32_t* __restrict__ BsrcH, const uint32_t* __restrict__ BsrcL, int bstr,
        uint32_t* P, float (&acc)[2][2][4], int tid, int wm, int wn, int g, int tg){
    int lr = tid>>2, lkp = (tid&3)*4;
    const uint32_t* pah = AsrcH + (size_t)lr*astr + lkp;
    const uint32_t* pal = AsrcL + (size_t)lr*astr + lkp;
    const uint32_t* pbh = BsrcH + (size_t)lr*bstr + lkp;
    const uint32_t* pbl = BsrcL + (size_t)lr*bstr + lkp;
    uint4 ra = *(const uint4*)pah;
    uint4 rb = *(const uint4*)pal;
    uint4 rc = *(const uint4*)pbh;
    uint4 rd = *(const uint4*)pbl;
    int o = lr*17 + lkp;
    #pragma unroll
    for(int c=0;c<NCHUNK;c++){
        uint32_t* buf = P + (c&1)*BUFSZ;
        buf[o+0]=ra.x; buf[o+1]=ra.y; buf[o+2]=ra.z; buf[o+3]=ra.w;
        buf[1088+o+0]=rb.x; buf[1088+o+1]=rb.y; buf[1088+o+2]=rb.z; buf[1088+o+3]=rb.w;
        buf[2176+o+0]=rc.x; buf[2176+o+1]=rc.y; buf[2176+o+2]=rc.z; buf[2176+o+3]=rc.w;
        buf[3264+o+0]=rd.x; buf[3264+o+1]=rd.y; buf[3264+o+2]=rd.z; buf[3264+o+3]=rd.w;
        __syncthreads();
        if(c+1<NCHUNK){
            ra = *(const uint4*)(pah + (c+1)*16);
            rb = *(const uint4*)(pal + (c+1)*16);
            rc = *(const uint4*)(pbh + (c+1)*16);
            rd = *(const uint4*)(pbl + (c+1)*16);
        }
        mma_block(buf, buf+1088, buf+2176, buf+3264, acc, wm, wn, g, tg);
    }
}

#define ACC_INIT(acc) { \
    _Pragma("unroll") for(int mi=0;mi<2;mi++) \
        _Pragma("unroll") for(int ni=0;ni<2;ni++) \
            _Pragma("unroll") for(int r=0;r<4;r++) acc[mi][ni][r]=0.f; }

#define ACC_TO_CS(acc, cs) { \
    _Pragma("unroll") for(int mi=0;mi<2;mi++){ \
        int r0 = wm*32+mi*16+g; \
        _Pragma("unroll") for(int ni=0;ni<2;ni++){ \
            int c0c = wn*16+ni*8+tg*2; \
            cs[r0*66+c0c]=acc[mi][ni][0];     cs[r0*66+c0c+1]=acc[mi][ni][1]; \
            cs[(r0+8)*66+c0c]=acc[mi][ni][2]; cs[(r0+8)*66+c0c+1]=acc[mi][ni][3]; \
        } } }

// =====================  xW GEMM (one-shot)  =====================
__global__ __launch_bounds__(256) void gemm_x(){
    __shared__ uint32_t P[2*BUFSZ];
    int tid=threadIdx.x;
    int m0=blockIdx.y*64, n0=blockIdx.x*64;
    int warp=tid>>5, lane=tid&31;
    int wm=warp>>2, wn=warp&3, g=lane>>2, tg=lane&3;
    float acc[2][2][4];
    ACC_INIT(acc);
    gemm_pipe<7>(g_Y5h + (size_t)m0*112, g_Y5l + (size_t)m0*112, 112,
                 g_WihH + (size_t)n0*112, g_WihL + (size_t)n0*112, 112,
                 P, acc, tid, wm, wn, g, tg);
    #pragma unroll
    for(int mi=0;mi<2;mi++){
        int row = m0+wm*32+mi*16+g;
        #pragma unroll
        for(int ni=0;ni<2;ni++){
            int col = n0+wn*16+ni*8+tg*2;
            float* p0 = g_xW + (size_t)row*896 + col;
            float* p1 = g_xW + (size_t)(row+8)*896 + col;
            p0[0]=acc[mi][ni][0]; p0[1]=acc[mi][ni][1];
            p1[0]=acc[mi][ni][2]; p1[1]=acc[mi][ni][3];
        }
    }
}

// =====================  encoder step (launch per t)  =====================
__global__ __launch_bounds__(256) void enc_step(int t){
    __shared__ uint32_t P[2*BUFSZ];
    float* cs = (float*)(P + BUFSZ);   // last mma (chunk 6) reads buffer 0
    int tid=threadIdx.x;
    int m0=blockIdx.y*64, n0=blockIdx.x*64;
    int warp=tid>>5, lane=tid&31;
    int wm=warp>>2, wn=warp&3, g=lane>>2, tg=lane&3;
    const uint32_t* srcH = g_Hh + (size_t)(t&1)*(BSZ*112);
    const uint32_t* srcL = g_Hl + (size_t)(t&1)*(BSZ*112);
    uint32_t* dstH = g_Hh + (size_t)((t+1)&1)*(BSZ*112);
    uint32_t* dstL = g_Hl + (size_t)((t+1)&1)*(BSZ*112);
    float acc[2][2][4];
    ACC_INIT(acc);
    gemm_pipe<7>(srcH + (size_t)m0*112, srcL + (size_t)m0*112, 112,
                 g_WhhH + (size_t)n0*112, g_WhhL + (size_t)n0*112, 112,
                 P, acc, tid, wm, wn, g, tg);
    ACC_TO_CS(acc, cs);
    __syncthreads();
    #pragma unroll 1
    for(int p=tid;p<512;p+=256){
        int m = p>>3, jp = p&7;
        int b = m0+m;
        const float* xw = g_xW + ((size_t)b*TT + t)*896 + n0 + 8*jp;
        float4 x0 = *(const float4*)xw;
        float4 x1 = *(const float4*)(xw+4);
        float4 s0 = *(const float4*)(g_bsE + n0 + 8*jp);
        float4 s1 = *(const float4*)(g_bsE + n0 + 8*jp + 4);
        const float* cp = cs + m*66 + 8*jp;
        float gi0=cp[0]+x0.x+s0.x, gf0=cp[1]+x0.y+s0.y, gg0=cp[2]+x0.z+s0.z, go0=cp[3]+x0.w+s0.w;
        float gi1=cp[4]+x1.x+s1.x, gf1=cp[5]+x1.y+s1.y, gg1=cp[6]+x1.z+s1.z, go1=cp[7]+x1.w+s1.w;
        int j0 = (n0>>2) + 2*jp;
        float c0v = g_c[(size_t)b*AD + j0];
        float c1v = g_c[(size_t)b*AD + j0 + 1];
        float cc0 = sigm(gf0)*c0v + sigm(gi0)*tanhf(gg0);
        float cc1 = sigm(gf1)*c1v + sigm(gi1)*tanhf(gg1);
        float h0v = sigm(go0)*tanhf(cc0);
        float h1v = sigm(go1)*tanhf(cc1);
        g_c[(size_t)b*AD + j0]   = cc0;
        g_c[(size_t)b*AD + j0+1] = cc1;
        float* yp = g_y8 + ((size_t)b*TT + t)*AD + j0;
        yp[0]=h0v; yp[1]=h1v;
        uint32_t hh,ll; splitpair(h0v,h1v,hh,ll);
        dstH[(size_t)b*112 + (n0>>3) + jp] = hh;
        dstL[(size_t)b*112 + (n0>>3) + jp] = ll;
    }
}

// =====================  decoder step GEMM+cell (launch per s)  =====================
__global__ __launch_bounds__(256) void dec_step(int s){
    __shared__ uint32_t P[2*BUFSZ];
    float* cs = (float*)(P + BUFSZ);   // last mma (chunk 14) reads buffer 0
    int tid=threadIdx.x;
    int m0=blockIdx.y*64, n0=blockIdx.x*64;
    int warp=tid>>5, lane=tid&31;
    int wm=warp>>2, wn=warp&3, g=lane>>2, tg=lane&3;
    const uint32_t* srcH = g_Ch + (size_t)(s&1)*(BSZ*240);
    const uint32_t* srcL = g_Cl + (size_t)(s&1)*(BSZ*240);
    uint32_t* dstH = g_Ch + (size_t)((s+1)&1)*(BSZ*240);
    uint32_t* dstL = g_Cl + (size_t)((s+1)&1)*(BSZ*240);
    float acc[2][2][4];
    ACC_INIT(acc);
    gemm_pipe<15>(srcH + (size_t)m0*240, srcL + (size_t)m0*240, 240,
                  g_WdH + (size_t)n0*240, g_WdL + (size_t)n0*240, 240,
                  P, acc, tid, wm, wn, g, tg);
    ACC_TO_CS(acc, cs);
    __syncthreads();
    #pragma unroll 1
    for(int p=tid;p<512;p+=256){
        int m = p>>3, jp = p&7;
        int b = m0+m;
        float4 s0 = *(const float4*)(g_bsD + n0 + 8*jp);
        float4 s1 = *(const float4*)(g_bsD + n0 + 8*jp + 4);
        const float* cp = cs + m*66 + 8*jp;
        float gi0=cp[0]+s0.x, gf0=cp[1]+s0.y, gg0=cp[2]+s0.z, go0=cp[3]+s0.w;
        float gi1=cp[4]+s1.x, gf1=cp[5]+s1.y, gg1=cp[6]+s1.z, go1=cp[7]+s1.w;
        int j0 = (n0>>2) + 2*jp;
        float c0v = g_dc[(size_t)b*HID + j0];
        float c1v = g_dc[(size_t)b*HID + j0 + 1];
        float cc0 = sigm(gf0)*c0v + sigm(gi0)*tanhf(gg0);
        float cc1 = sigm(gf1)*c1v + sigm(gi1)*tanhf(gg1);
        float h0v = sigm(go0)*tanhf(cc0);
        float h1v = sigm(go1)*tanhf(cc1);
        g_dc[(size_t)b*HID + j0]   = cc0;
        g_dc[(size_t)b*HID + j0+1] = cc1;
        g_dh[(size_t)b*HID + j0]   = h0v;
        g_dh[(size_t)b*HID + j0+1] = h1v;
        uint32_t hh,ll; splitpair(h0v,h1v,hh,ll);
        dstH[(size_t)b*240 + 112 + (n0>>3) + jp] = hh;
        dstL[(size_t)b*240 + 112 + (n0>>3) + jp] = ll;
    }
}

// =====================  fused attention + output projection  =====================
__global__ __launch_bounds__(256) void attn_out_k(const float* __restrict__ attw,
        const float* __restrict__ attb, const float* __restrict__ outw,
        const float* __restrict__ outb, float* __restrict__ out, int s){
    int b = blockIdx.x, tid = threadIdx.x;
    __shared__ float dh_s[256];
    __shared__ float red[256];
    __shared__ float sc[TT];
    __shared__ float ctx_s[AD];
    dh_s[tid] = g_dh[(size_t)b*HID + tid];
    __syncthreads();

    if(s < OUT_LEN){
        red[tid] = dh_s[tid]*__ldg(attw+tid);
        __syncthreads();
        #pragma unroll
        for(int r=128;r>0;r>>=1){ if(tid<r) red[tid]+=red[tid+r]; __syncthreads(); }
        float hw = red[0] + __ldg(attb);
        if(tid < 32){
            float x = g_escore[b*TT + tid] + hw;
            float mx = x;
            #pragma unroll
            for(int o=16;o>0;o>>=1) mx = fmaxf(mx,__shfl_xor_sync(0xffffffffu,mx,o));
            float e = expf(x-mx), sm = e;
            #pragma unroll
            for(int o=16;o>0;o>>=1) sm += __shfl_xor_sync(0xffffffffu,sm,o);
            sc[tid] = e/sm;
        }
        __syncthreads();
        if(tid < AD){
            const float* y = g_y8 + (size_t)b*TT*AD + tid;
            float acc=0.f;
            #pragma unroll
            for(int t=0;t<TT;t++) acc = fmaf(sc[t], y[t*AD], acc);
            ctx_s[tid]=acc;
        }
        __syncthreads();
        if(tid < 112){
            uint32_t hh,ll; splitpair(ctx_s[2*tid], ctx_s[2*tid+1], hh, ll);
            g_Ch[(size_t)(s&1)*(BSZ*240) + (size_t)b*240 + tid] = hh;
            g_Cl[(size_t)(s&1)*(BSZ*240) + (size_t)b*240 + tid] = ll;
        }
    }
    if(s > 0){
        int w = tid>>5, lane = tid&31;
        #pragma unroll
        for(int v=w; v<VOCAB; v+=8){
            const float* wp = outw + (size_t)v*HID;
            float sum = 0.f;
            #pragma unroll
            for(int q=0;q<8;q++) sum = fmaf(dh_s[lane+32*q], __ldg(wp+lane+32*q), sum);
            #pragma unroll
            for(int o=16;o>0;o>>=1) sum += __shfl_xor_sync(0xffffffffu,sum,o);
            if(lane==0)
                out[(size_t)b*VOCAB*OUT_LEN + v*OUT_LEN + (s-1)] = sum + __ldg(outb+v);
        }
    }
}

// =====================  launch  =====================
extern "C" void kernel_launch(void* const* d_in, const int* in_sizes, int n_in,
                              void* d_out, int out_size){
    const float* x       = (const float*)d_in[0];
    const float* c1w     = (const float*)d_in[1];
    const float* c1b     = (const float*)d_in[2];
    const float* c2w     = (const float*)d_in[3];
    const float* c2b     = (const float*)d_in[4];
    const float* c3w     = (const float*)d_in[5];
    const float* c3b     = (const float*)d_in[6];
    const float* c4w     = (const float*)d_in[7];
    const float* c4b     = (const float*)d_in[8];
    const float* h0      = (const float*)d_in[9];
    const float* c0      = (const float*)d_in[10];
    const float* lstmWih = (const float*)d_in[11];
    const float* lstmWhh = (const float*)d_in[12];
    const float* lstmbih = (const float*)d_in[13];
    const float* lstmbhh = (const float*)d_in[14];
    const float* attw    = (const float*)d_in[15];
    const float* attb    = (const float*)d_in[16];
    const float* decWih  = (const float*)d_in[17];
    const float* decWhh  = (const float*)d_in[18];
    const float* decbih  = (const float*)d_in[19];
    const float* decbhh  = (const float*)d_in[20];
    const float* outw    = (const float*)d_in[21];
    const float* outb    = (const float*)d_in[22];
    float* out = (float*)d_out;

    float *y1,*y2,*y3,*y5;
    uint32_t *Y5h,*Y5l;
    cudaGetSymbolAddress((void**)&y1,  g_y1);
    cudaGetSymbolAddress((void**)&y2,  g_y2);
    cudaGetSymbolAddress((void**)&y3,  g_y3);
    cudaGetSymbolAddress((void**)&y5,  g_y5);
    cudaGetSymbolAddress((void**)&Y5h, g_Y5h);
    cudaGetSymbolAddress((void**)&Y5l, g_Y5l);

    // merged weight prep (1 launch)
    prep_k<<<(SEG5+255)/256,256>>>(lstmWih, lstmWhh, decWih, decWhh,
                                   lstmbih, lstmbhh, decbih, decbhh);

    // conv stack
    conv1_k<<<BSZ*6,256>>>(x,  c1w, c1b, y1);
    conv2_k<<<BSZ*6,256>>>(y1, c2w, c2b, y2);
    conv3_k<<<BSZ*4,256>>>(y2, c3w, c3b, y3);
    conv4_k<<<BSZ,  256>>>(y3, c4w, c4b, y5);

    // split y5 then xW GEMM
    split_a_k<<<(BSZ*TT*112+255)/256,256>>>(y5, Y5h, Y5l, BSZ*TT*112);
    gemm_x<<<dim3(14,512),256>>>();

    // encoder scan
    init_enc_k<<<(BSZ*AD+255)/256,256>>>(h0, c0);
    for(int t=0;t<TT;t++)
        enc_step<<<dim3(14,16),256>>>(t);

    // attention precompute + decoder init
    enc_score_k<<<(BSZ*TT*32+255)/256,256>>>(attw);
    init_dec_k<<<(BSZ*HID+255)/256,256>>>();

    // decoder scan: attn(s)+out(s-1), then gemm+cell(s); final launch emits out(24)
    for(int s=0;s<=OUT_LEN;s++){
        attn_out_k<<<BSZ,256>>>(attw, attb, outw, outb, out, s);
        if(s<OUT_LEN) dec_step<<<dim3(16,16),256>>>(s);
    }
}

// round 13
// speedup vs baseline: 1.3383x; 1.0165x over previous
#include <cuda_runtime.h>
#include <cuda_bf16.h>
#include <cstdint>

#define BSZ  1024
#define TT   32
#define AD   224
#define HID  256
#define VOCAB 29
#define OUT_LEN 25

// ---------------- scratch (device globals) ----------------
__device__ float g_y1[BSZ*4*192*28];
__device__ float g_y2[BSZ*16*96*14];
__device__ float g_y3[BSZ*16*32*7];
__device__ float g_y5[BSZ*TT*AD];
__device__ __align__(16) float g_xW[BSZ*TT*896];
__device__ __align__(16) float g_y8[BSZ*TT*AD];
__device__ float g_escore[BSZ*TT];
__device__ float g_c [BSZ*AD];
__device__ float g_dh[BSZ*HID];
__device__ float g_dc[BSZ*HID];
// pre-split activations (bf16 hi/lo pairs packed as u32)
__device__ __align__(16) uint32_t g_Y5h[BSZ*TT*112], g_Y5l[BSZ*TT*112];
__device__ __align__(16) uint32_t g_Hh[2*BSZ*112],   g_Hl[2*BSZ*112];
__device__ __align__(16) uint32_t g_Ch[2*BSZ*240],   g_Cl[2*BSZ*240];
// pre-split weights, gate-interleaved rows
__device__ __align__(16) uint32_t g_WihH[896*112], g_WihL[896*112];
__device__ __align__(16) uint32_t g_WhhH[896*112], g_WhhL[896*112];
__device__ __align__(16) uint32_t g_WdH[1024*240], g_WdL[1024*240];
__device__ __align__(16) float g_bsE[896], g_bsD[1024];

__device__ __forceinline__ float sigm(float x){ return 1.0f/(1.0f+expf(-x)); }
// packed f32x2 FMA: bit-identical to scalar rn FMA
__device__ __forceinline__ void ffma4p(float4& a, const float4& x, const float4& w){
    unsigned long long* ap = reinterpret_cast<unsigned long long*>(&a);
    const unsigned long long* xp = reinterpret_cast<const unsigned long long*>(&x);
    const unsigned long long* wp = reinterpret_cast<const unsigned long long*>(&w);
    asm("fma.rn.f32x2 %0, %1, %2, %0;" : "+l"(ap[0]) : "l"(xp[0]), "l"(wp[0]));
    asm("fma.rn.f32x2 %0, %1, %2, %0;" : "+l"(ap[1]) : "l"(xp[1]), "l"(wp[1]));
}
__device__ __forceinline__ float hsum4(float4 a){ return a.x+a.y+a.z+a.w; }
__device__ __forceinline__ void splitpair(float x, float y, uint32_t& hi, uint32_t& lo){
    __nv_bfloat162 h = __floats2bfloat162_rn(x, y);
    __nv_bfloat162 l = __floats2bfloat162_rn(x - __bfloat162float(h.x), y - __bfloat162float(h.y));
    hi = *reinterpret_cast<uint32_t*>(&h);
    lo = *reinterpret_cast<uint32_t*>(&l);
}

// =====================  CONV STACK (exact R10/R12 versions)  =====================
__global__ __launch_bounds__(256) void conv1_k(const float* __restrict__ x,
        const float* __restrict__ cw, const float* __restrict__ cb, float* __restrict__ out){
    __shared__ float xin[66*30];
    __shared__ float w_s[36];
    __shared__ float b_s[4];
    int b = blockIdx.x/6, pho0 = (blockIdx.x%6)*32;
    int tid = threadIdx.x, lane = tid&31, warp = tid>>5;
    for(int f=tid; f<66*30; f+=256){
        int rr=f/30, cc=f%30;
        int gr=pho0*2-1+rr, gc=cc-1;
        float v=0.f;
        if(gr>=0 && gr<384 && gc>=0 && gc<28) v = x[((size_t)b*384+gr)*28+gc];
        xin[f]=v;
    }
    if(tid<36) w_s[tid]=cw[tid];
    if(tid<4)  b_s[tid]=cb[tid];
    __syncthreads();
    int wo = min(lane,27);
    for(int it=warp; it<128; it+=8){
        int oc=it>>5, ph=it&31;
        float wr[9];
        #pragma unroll
        for(int k=0;k<9;k++) wr[k]=w_s[oc*9+k];
        float bv=b_s[oc], s0=bv, s1=bv;
        #pragma unroll
        for(int kw=0;kw<3;kw++){
            float X[4];
            #pragma unroll
            for(int r=0;r<4;r++) X[r]=xin[(2*ph+r)*30+wo+kw];
            #pragma unroll
            for(int kh=0;kh<3;kh++){
                s0=fmaf(X[kh],  wr[kh*3+kw],s0);
                s1=fmaf(X[kh+1],wr[kh*3+kw],s1);
            }
        }
        float m = fmaxf(fmaxf(s0,0.f), fmaxf(s1,0.f));
        if(lane<28) out[((size_t)(b*4+oc)*192+pho0+ph)*28+wo]=m;
    }
}

__global__ __launch_bounds__(256) void conv2_k(const float* __restrict__ in,
        const float* __restrict__ cw, const float* __restrict__ cb, float* __restrict__ out){
    __shared__ float4 xin[34*30];
    __shared__ float4 w_s[144];
    __shared__ float  b_s[16];
    int b = blockIdx.x/6, pho0 = (blockIdx.x%6)*16;
    int tid = threadIdx.x, lane = tid&31, warp = tid>>5;
    for(int f=tid; f<34*30; f+=256){
        int rr=f/30, cc=f%30;
        int gr=pho0*2-1+rr, gc=cc-1;
        float4 v={0,0,0,0};
        if(gr>=0 && gr<192 && gc>=0 && gc<28){
            const float* p = in + ((size_t)b*4*192+gr)*28+gc;
            v.x=p[0]; v.y=p[192*28]; v.z=p[2*192*28]; v.w=p[3*192*28];
        }
        xin[f]=v;
    }
    for(int f=tid; f<144; f+=256){
        int oc=f/9, k=f%9;
        float4 v; v.x=cw[(oc*4+0)*9+k]; v.y=cw[(oc*4+1)*9+k];
                  v.z=cw[(oc*4+2)*9+k]; v.w=cw[(oc*4+3)*9+k];
        w_s[f]=v;
    }
    if(tid<16) b_s[tid]=cb[tid];
    __syncthreads();
    int wc = min(lane,27);
    int oc0 = warp, oc1 = warp+8;
    float bv0 = b_s[oc0], bv1 = b_s[oc1];
    #pragma unroll 1
    for(int pp=0; pp<8; pp++){
        float4 a[2][4];
        #pragma unroll
        for(int o=0;o<2;o++)
            #pragma unroll
            for(int r=0;r<4;r++) a[o][r]=make_float4(0,0,0,0);
        #pragma unroll
        for(int kw=0;kw<3;kw++){
            float4 X[6];
            #pragma unroll
            for(int r=0;r<6;r++) X[r]=xin[(pp*4+r)*30+wc+kw];
            #pragma unroll
            for(int kh=0;kh<3;kh++){
                float4 w0=w_s[oc0*9+kh*3+kw];
                float4 w1=w_s[oc1*9+kh*3+kw];
                ffma4p(a[0][0],X[kh],w0); ffma4p(a[0][1],X[kh+1],w0);
                ffma4p(a[0][2],X[kh+2],w0); ffma4p(a[0][3],X[kh+3],w0);
                ffma4p(a[1][0],X[kh],w1); ffma4p(a[1][1],X[kh+1],w1);
                ffma4p(a[1][2],X[kh+2],w1); ffma4p(a[1][3],X[kh+3],w1);
            }
        }
        #pragma unroll
        for(int o=0;o<2;o++){
            int oc = o ? oc1 : oc0;
            float bv = o ? bv1 : bv0;
            float s0=hsum4(a[o][0])+bv, s1=hsum4(a[o][1])+bv;
            float s2=hsum4(a[o][2])+bv, s3=hsum4(a[o][3])+bv;
            float p0=fmaxf(fmaxf(s0,0.f),fmaxf(s1,0.f));
            float p1=fmaxf(fmaxf(s2,0.f),fmaxf(s3,0.f));
            float q0=fmaxf(p0, __shfl_down_sync(0xffffffffu,p0,1));
            float q1=fmaxf(p1, __shfl_down_sync(0xffffffffu,p1,1));
            if(!(lane&1) && lane<28){
                int wo=wc>>1;
                out[((size_t)(b*16+oc)*96+pho0+2*pp+0)*14+wo]=q0;
                out[((size_t)(b*16+oc)*96+pho0+2*pp+1)*14+wo]=q1;
            }
        }
    }
}

__global__ __launch_bounds__(256) void conv3_k(const float* __restrict__ in,
        const float* __restrict__ cw, const float* __restrict__ cb, float* __restrict__ out){
    __shared__ float4 xin[4*26*16];
    __shared__ float4 w_s[576];
    __shared__ float  b_s[16];
    int b = blockIdx.x>>2, pho0 = (blockIdx.x&3)*8;
    int tid = threadIdx.x, lane = tid&31, warp = tid>>5;
    for(int f=tid; f<4*26*16; f+=256){
        int icg=f/(26*16), rr=(f/16)%26, cc=f%16;
        int gr=pho0*3-1+rr, gc=cc-1;
        float4 v={0,0,0,0};
        if(gr>=0 && gr<96 && gc>=0 && gc<14){
            const float* p = in + ((size_t)(b*16+icg*4)*96+gr)*14+gc;
            v.x=p[0]; v.y=p[96*14]; v.z=p[2*96*14]; v.w=p[3*96*14];
        }
        xin[f]=v;
    }
    for(int f=tid; f<576; f+=256){
        int oc=f/36, icg=(f/9)%4, k=f%9;
        float4 v;
        v.x=cw[(oc*16+icg*4+0)*9+k]; v.y=cw[(oc*16+icg*4+1)*9+k];
        v.z=cw[(oc*16+icg*4+2)*9+k]; v.w=cw[(oc*16+icg*4+3)*9+k];
        w_s[f]=v;
    }
    if(tid<16) b_s[tid]=cb[tid];
    __syncthreads();
    int half = lane>>4;
    int hw = warp*2 + half;           // 0..15
    int wc = min(lane&15, 13);
    #pragma unroll 1
    for(int it=hw; it<64; it+=16){
        int pair = it>>3, ph = it&7;
        int oc0 = pair, oc1 = pair+8;
        float4 acc[2][3];
        #pragma unroll
        for(int o=0;o<2;o++)
            #pragma unroll
            for(int r=0;r<3;r++) acc[o][r]=make_float4(0,0,0,0);
        #pragma unroll
        for(int icg=0;icg<4;icg++){
            #pragma unroll
            for(int kw=0;kw<3;kw++){
                float4 X[5];
                #pragma unroll
                for(int r=0;r<5;r++) X[r]=xin[(icg*26+3*ph+r)*16+wc+kw];
                #pragma unroll
                for(int kh=0;kh<3;kh++){
                    float4 w0=w_s[(oc0*4+icg)*9+kh*3+kw];
                    float4 w1=w_s[(oc1*4+icg)*9+kh*3+kw];
                    ffma4p(acc[0][0],X[kh],w0);
                    ffma4p(acc[0][1],X[kh+1],w0);
                    ffma4p(acc[0][2],X[kh+2],w0);
                    ffma4p(acc[1][0],X[kh],w1);
                    ffma4p(acc[1][1],X[kh+1],w1);
                    ffma4p(acc[1][2],X[kh+2],w1);
                }
            }
        }
        #pragma unroll
        for(int o=0;o<2;o++){
            int oc = o ? oc1 : oc0;
            float bv = b_s[oc];
            float s0=fmaxf(hsum4(acc[o][0])+bv,0.f);
            float s1=fmaxf(hsum4(acc[o][1])+bv,0.f);
            float s2=fmaxf(hsum4(acc[o][2])+bv,0.f);
            float v=fmaxf(fmaxf(s0,s1),s2);
            float ov=fmaxf(v, __shfl_down_sync(0xffffffffu,v,1));
            if(!(lane&1) && (lane&15)<14)
                out[((size_t)(b*16+oc)*32+pho0+ph)*7+(wc>>1)]=ov;
        }
    }
}

__global__ __launch_bounds__(256) void conv4_k(const float* __restrict__ in,
        const float* __restrict__ cw, const float* __restrict__ cb, float* __restrict__ out){
    __shared__ float4 xin[4*34*9];
    __shared__ float4 w_s[1152];
    __shared__ float  b_s[32];
    int b = blockIdx.x;
    int tid = threadIdx.x, lane = tid&31, warp = tid>>5;
    for(int f=tid; f<4*34*9; f+=256){
        int icg=f/(34*9), rr=(f/9)%34, cc=f%9;
        int gr=rr-1, gc=cc-1;
        float4 v={0,0,0,0};
        if(gr>=0 && gr<32 && gc>=0 && gc<7){
            const float* p = in + ((size_t)(b*16+icg*4)*32+gr)*7+gc;
            v.x=p[0]; v.y=p[32*7]; v.z=p[2*32*7]; v.w=p[3*32*7];
        }
        xin[f]=v;
    }
    for(int f=tid; f<1152; f+=256){
        int oc=f/36, icg=(f/9)%4, k=f%9;
        float4 v;
        v.x=cw[(oc*16+icg*4+0)*9+k]; v.y=cw[(oc*16+icg*4+1)*9+k];
        v.z=cw[(oc*16+icg*4+2)*9+k]; v.w=cw[(oc*16+icg*4+3)*9+k];
        w_s[f]=v;
    }
    if(tid<32) b_s[tid]=cb[tid];
    __syncthreads();
    int quarter = lane>>3;
    int qw = warp*4 + quarter;        // 0..31
    int wc = min(lane&7, 6);
    #pragma unroll 1
    for(int it=qw; it<128; it+=32){
        int pair = it>>3, hq = it&7;
        int oc0 = pair, oc1 = pair+16;
        float4 ac[2][4];
        #pragma unroll
        for(int o=0;o<2;o++)
            #pragma unroll
            for(int r=0;r<4;r++) ac[o][r]=make_float4(0,0,0,0);
        #pragma unroll
        for(int icg=0;icg<4;icg++){
            #pragma unroll
            for(int kw=0;kw<3;kw++){
                float4 X[6];
                #pragma unroll
                for(int r=0;r<6;r++) X[r]=xin[(icg*34+4*hq+r)*9+wc+kw];
                #pragma unroll
                for(int kh=0;kh<3;kh++){
                    float4 w0=w_s[(oc0*4+icg)*9+kh*3+kw];
                    float4 w1=w_s[(oc1*4+icg)*9+kh*3+kw];
                    #pragma unroll
                    for(int r=0;r<4;r++) ffma4p(ac[0][r],X[r+kh],w0);
                    #pragma unroll
                    for(int r=0;r<4;r++) ffma4p(ac[1][r],X[r+kh],w1);
                }
            }
        }
        #pragma unroll
        for(int o=0;o<2;o++){
            int oc = o ? oc1 : oc0;
            float bv = b_s[oc];
            #pragma unroll
            for(int r=0;r<4;r++){
                float s=fmaxf(hsum4(ac[o][r])+bv,0.f);
                if((lane&7)<7)
                    out[((size_t)b*32+hq*4+r)*224+wc*32+oc]=s;
            }
        }
    }
}

// =====================  merged prep kernel  =====================
#define SEG0 100352
#define SEG1 (SEG0+100352)
#define SEG2 (SEG1+114688)
#define SEG3 (SEG2+131072)
#define SEG4 (SEG3+896)
#define SEG5 (SEG4+1024)
__global__ void prep_k(const float* __restrict__ lstmWih, const float* __restrict__ lstmWhh,
        const float* __restrict__ decWih, const float* __restrict__ decWhh,
        const float* __restrict__ lstmbih, const float* __restrict__ lstmbhh,
        const float* __restrict__ decbih, const float* __restrict__ decbhh){
    int idx = blockIdx.x*blockDim.x+threadIdx.x;
    if(idx >= SEG5) return;
    if(idx < SEG3){
        const float* W; uint32_t *Wh, *Wl;
        int base, kp2, kstride, gatesize;
        if(idx < SEG0){ W=lstmWih; Wh=g_WihH; Wl=g_WihL; base=0;    kp2=112; kstride=112; gatesize=224; }
        else if(idx < SEG1){ W=lstmWhh; Wh=g_WhhH; Wl=g_WhhL; base=SEG0; kp2=112; kstride=112; gatesize=224; }
        else if(idx < SEG2){ W=decWih;  Wh=g_WdH;  Wl=g_WdL;  base=SEG1; kp2=112; kstride=240; gatesize=256; }
        else { W=decWhh; Wh=g_WdH+112; Wl=g_WdL+112; base=SEG2; kp2=128; kstride=240; gatesize=256; }
        int li = idx - base;
        int kp = li%kp2, np = li/kp2;
        int Ksrc = kp2*2;
        int j=np>>2, gg=np&3;
        int srow = gg*gatesize+j;
        float x = W[(size_t)srow*Ksrc+2*kp], y = W[(size_t)srow*Ksrc+2*kp+1];
        uint32_t h,l; splitpair(x,y,h,l);
        Wh[(size_t)np*kstride+kp]=h; Wl[(size_t)np*kstride+kp]=l;
    } else if(idx < SEG4){
        int np = idx - SEG3;
        int j=np>>2, gg=np&3, s=gg*224+j;
        g_bsE[np] = lstmbih[s]+lstmbhh[s];
    } else {
        int np = idx - SEG4;
        int j=np>>2, gg=np&3, s=gg*256+j;
        g_bsD[np] = decbih[s]+decbhh[s];
    }
}

__global__ void split_a_k(const float* __restrict__ A, uint32_t* __restrict__ Ahi,
                          uint32_t* __restrict__ Alo, int total){
    int idx = blockIdx.x*blockDim.x+threadIdx.x;
    if(idx>=total) return;
    uint32_t h,l; splitpair(A[2*idx], A[2*idx+1], h, l);
    Ahi[idx]=h; Alo[idx]=l;
}
__global__ void init_enc_k(const float* __restrict__ h0, const float* __restrict__ c0){
    int idx = blockIdx.x*blockDim.x+threadIdx.x;
    if(idx < BSZ*AD) g_c[idx] = __ldg(c0 + idx%AD);
    if(idx < BSZ*112){
        int k = idx%112;
        uint32_t h,l; splitpair(__ldg(h0+2*k), __ldg(h0+2*k+1), h, l);
        g_Hh[idx]=h; g_Hl[idx]=l;
    }
}
__global__ void init_dec_k(){
    int idx = blockIdx.x*blockDim.x+threadIdx.x;
    if(idx>=BSZ*HID) return;
    g_dh[idx]=0.f; g_dc[idx]=0.f;
    int k = idx&255;
    if(k<128){ g_Ch[(idx>>8)*240+112+k]=0u; g_Cl[(idx>>8)*240+112+k]=0u; }
}
__global__ void enc_score_k(const float* __restrict__ att_w){
    int gl = blockIdx.x*blockDim.x+threadIdx.x;
    int row = gl>>5, lane = gl&31;
    if(row>=BSZ*TT) return;
    const float* r = g_y8 + (size_t)row*AD;
    const float* we = att_w + HID;
    float s=0.f;
    for(int k=lane;k<AD;k+=32) s += r[k]*__ldg(we+k);
    #pragma unroll
    for(int o=16;o>0;o>>=1) s += __shfl_xor_sync(0xffffffffu,s,o);
    if(lane==0) g_escore[row]=s;
}

// =====================  MMA core (256-thread blocks, 8 warps, 64x64 tile)  =====================
#define MMA(c, a, b) asm volatile( \
    "mma.sync.aligned.m16n8k16.row.col.f32.bf16.bf16.f32 " \
    "{%0,%1,%2,%3},{%4,%5,%6,%7},{%8,%9},{%0,%1,%2,%3};" \
    : "+f"(c[0]),"+f"(c[1]),"+f"(c[2]),"+f"(c[3]) \
    : "r"(a[0]),"r"(a[1]),"r"(a[2]),"r"(a[3]),"r"(b[0]),"r"(b[1]))

__device__ __forceinline__ void mma_block(const uint32_t* __restrict__ Ah,
        const uint32_t* __restrict__ Al, const uint32_t* __restrict__ Bh,
        const uint32_t* __restrict__ Bl,
        float (&acc)[2][2][4], int wm, int wn, int g, int tg){
    #pragma unroll
    for(int kk=0;kk<2;kk++){
        uint32_t aH[2][4], aL[2][4], bH[2][2], bL[2][2];
        int kp = kk*8+tg;
        #pragma unroll
        for(int mi=0;mi<2;mi++){
            int r0 = wm*32+mi*16+g;
            aH[mi][0]=Ah[r0*17+kp];   aH[mi][1]=Ah[(r0+8)*17+kp];
            aH[mi][2]=Ah[r0*17+kp+4]; aH[mi][3]=Ah[(r0+8)*17+kp+4];
            aL[mi][0]=Al[r0*17+kp];   aL[mi][1]=Al[(r0+8)*17+kp];
            aL[mi][2]=Al[r0*17+kp+4]; aL[mi][3]=Al[(r0+8)*17+kp+4];
        }
        #pragma unroll
        for(int ni=0;ni<2;ni++){
            int c0 = wn*16+ni*8+g;
            bH[ni][0]=Bh[c0*17+kp]; bH[ni][1]=Bh[c0*17+kp+4];
            bL[ni][0]=Bl[c0*17+kp]; bL[ni][1]=Bl[c0*17+kp+4];
        }
        #pragma unroll
        for(int mi=0;mi<2;mi++)
            #pragma unroll
            for(int ni=0;ni<2;ni++){
                MMA(acc[mi][ni], aH[mi], bH[ni]);
                MMA(acc[mi][ni], aL[mi], bH[ni]);
                MMA(acc[mi][ni], aH[mi], bL[ni]);
            }
    }
}

// ---- double-buffered pipelined mainloop; PDL: B prefetch -> gridsync -> A loads ----
#define BUFSZ (4*64*17)

template<int NCHUNK, bool PDL>
__device__ __forceinline__ void gemm_pipe(
        const uint32_t* __restrict__ AsrcH, const uint32_t* __restrict__ AsrcL, int astr,
        const uint32_t* __restrict__ BsrcH, const uint32_t* __restrict__ BsrcL, int bstr,
        uint32_t* P, float (&acc)[2][2][4], int tid, int wm, int wn, int g, int tg){
    int lr = tid>>2, lkp = (tid&3)*4;
    const uint32_t* pah = AsrcH + (size_t)lr*astr + lkp;
    const uint32_t* pal = AsrcL + (size_t)lr*astr + lkp;
    const uint32_t* pbh = BsrcH + (size_t)lr*bstr + lkp;
    const uint32_t* pbl = BsrcL + (size_t)lr*bstr + lkp;
    uint4 rc = *(const uint4*)pbh;        // weights: step-invariant, safe pre-sync
    uint4 rd = *(const uint4*)pbl;
    if(PDL) cudaGridDependencySynchronize();
    uint4 ra = *(const uint4*)pah;        // activations: depend on predecessor
    uint4 rb = *(const uint4*)pal;
    int o = lr*17 + lkp;
    #pragma unroll
    for(int c=0;c<NCHUNK;c++){
        uint32_t* buf = P + (c&1)*BUFSZ;
        buf[o+0]=ra.x; buf[o+1]=ra.y; buf[o+2]=ra.z; buf[o+3]=ra.w;
        buf[1088+o+0]=rb.x; buf[1088+o+1]=rb.y; buf[1088+o+2]=rb.z; buf[1088+o+3]=rb.w;
        buf[2176+o+0]=rc.x; buf[2176+o+1]=rc.y; buf[2176+o+2]=rc.z; buf[2176+o+3]=rc.w;
        buf[3264+o+0]=rd.x; buf[3264+o+1]=rd.y; buf[3264+o+2]=rd.z; buf[3264+o+3]=rd.w;
        __syncthreads();
        if(c+1<NCHUNK){
            ra = *(const uint4*)(pah + (c+1)*16);
            rb = *(const uint4*)(pal + (c+1)*16);
            rc = *(const uint4*)(pbh + (c+1)*16);
            rd = *(const uint4*)(pbl + (c+1)*16);
        }
        mma_block(buf, buf+1088, buf+2176, buf+3264, acc, wm, wn, g, tg);
    }
}

#define ACC_INIT(acc) { \
    _Pragma("unroll") for(int mi=0;mi<2;mi++) \
        _Pragma("unroll") for(int ni=0;ni<2;ni++) \
            _Pragma("unroll") for(int r=0;r<4;r++) acc[mi][ni][r]=0.f; }

#define ACC_TO_CS(acc, cs) { \
    _Pragma("unroll") for(int mi=0;mi<2;mi++){ \
        int r0 = wm*32+mi*16+g; \
        _Pragma("unroll") for(int ni=0;ni<2;ni++){ \
            int c0c = wn*16+ni*8+tg*2; \
            cs[r0*66+c0c]=acc[mi][ni][0];     cs[r0*66+c0c+1]=acc[mi][ni][1]; \
            cs[(r0+8)*66+c0c]=acc[mi][ni][2]; cs[(r0+8)*66+c0c+1]=acc[mi][ni][3]; \
        } } }

// =====================  xW GEMM (one-shot)  =====================
__global__ __launch_bounds__(256) void gemm_x(){
    __shared__ uint32_t P[2*BUFSZ];
    int tid=threadIdx.x;
    int m0=blockIdx.y*64, n0=blockIdx.x*64;
    int warp=tid>>5, lane=tid&31;
    int wm=warp>>2, wn=warp&3, g=lane>>2, tg=lane&3;
    float acc[2][2][4];
    ACC_INIT(acc);
    gemm_pipe<7,false>(g_Y5h + (size_t)m0*112, g_Y5l + (size_t)m0*112, 112,
                 g_WihH + (size_t)n0*112, g_WihL + (size_t)n0*112, 112,
                 P, acc, tid, wm, wn, g, tg);
    #pragma unroll
    for(int mi=0;mi<2;mi++){
        int row = m0+wm*32+mi*16+g;
        #pragma unroll
        for(int ni=0;ni<2;ni++){
            int col = n0+wn*16+ni*8+tg*2;
            float* p0 = g_xW + (size_t)row*896 + col;
            float* p1 = g_xW + (size_t)(row+8)*896 + col;
            p0[0]=acc[mi][ni][0]; p0[1]=acc[mi][ni][1];
            p1[0]=acc[mi][ni][2]; p1[1]=acc[mi][ni][3];
        }
    }
}

// =====================  encoder step (launch per t, PDL)  =====================
__global__ __launch_bounds__(256) void enc_step(int t){
    __shared__ uint32_t P[2*BUFSZ];
    float* cs = (float*)(P + BUFSZ);   // last mma (chunk 6) reads buffer 0
    int tid=threadIdx.x;
    int m0=blockIdx.y*64, n0=blockIdx.x*64;
    int warp=tid>>5, lane=tid&31;
    int wm=warp>>2, wn=warp&3, g=lane>>2, tg=lane&3;
    const uint32_t* srcH = g_Hh + (size_t)(t&1)*(BSZ*112);
    const uint32_t* srcL = g_Hl + (size_t)(t&1)*(BSZ*112);
    uint32_t* dstH = g_Hh + (size_t)((t+1)&1)*(BSZ*112);
    uint32_t* dstL = g_Hl + (size_t)((t+1)&1)*(BSZ*112);
    float acc[2][2][4];
    ACC_INIT(acc);
    gemm_pipe<7,true>(srcH + (size_t)m0*112, srcL + (size_t)m0*112, 112,
                 g_WhhH + (size_t)n0*112, g_WhhL + (size_t)n0*112, 112,
                 P, acc, tid, wm, wn, g, tg);
    ACC_TO_CS(acc, cs);
    __syncthreads();
    #pragma unroll 1
    for(int p=tid;p<512;p+=256){
        int m = p>>3, jp = p&7;
        int b = m0+m;
        const float* xw = g_xW + ((size_t)b*TT + t)*896 + n0 + 8*jp;
        float4 x0 = *(const float4*)xw;
        float4 x1 = *(const float4*)(xw+4);
        float4 s0 = *(const float4*)(g_bsE + n0 + 8*jp);
        float4 s1 = *(const float4*)(g_bsE + n0 + 8*jp + 4);
        const float* cp = cs + m*66 + 8*jp;
        float gi0=cp[0]+x0.x+s0.x, gf0=cp[1]+x0.y+s0.y, gg0=cp[2]+x0.z+s0.z, go0=cp[3]+x0.w+s0.w;
        float gi1=cp[4]+x1.x+s1.x, gf1=cp[5]+x1.y+s1.y, gg1=cp[6]+x1.z+s1.z, go1=cp[7]+x1.w+s1.w;
        int j0 = (n0>>2) + 2*jp;
        float c0v = g_c[(size_t)b*AD + j0];
        float c1v = g_c[(size_t)b*AD + j0 + 1];
        float cc0 = sigm(gf0)*c0v + sigm(gi0)*tanhf(gg0);
        float cc1 = sigm(gf1)*c1v + sigm(gi1)*tanhf(gg1);
        float h0v = sigm(go0)*tanhf(cc0);
        float h1v = sigm(go1)*tanhf(cc1);
        g_c[(size_t)b*AD + j0]   = cc0;
        g_c[(size_t)b*AD + j0+1] = cc1;
        float* yp = g_y8 + ((size_t)b*TT + t)*AD + j0;
        yp[0]=h0v; yp[1]=h1v;
        uint32_t hh,ll; splitpair(h0v,h1v,hh,ll);
        dstH[(size_t)b*112 + (n0>>3) + jp] = hh;
        dstL[(size_t)b*112 + (n0>>3) + jp] = ll;
    }
}

// =====================  decoder step GEMM+cell (launch per s, PDL)  =====================
__global__ __launch_bounds__(256) void dec_step(int s){
    __shared__ uint32_t P[2*BUFSZ];
    float* cs = (float*)(P + BUFSZ);   // last mma (chunk 14) reads buffer 0
    int tid=threadIdx.x;
    int m0=blockIdx.y*64, n0=blockIdx.x*64;
    int warp=tid>>5, lane=tid&31;
    int wm=warp>>2, wn=warp&3, g=lane>>2, tg=lane&3;
    const uint32_t* srcH = g_Ch + (size_t)(s&1)*(BSZ*240);
    const uint32_t* srcL = g_Cl + (size_t)(s&1)*(BSZ*240);
    uint32_t* dstH = g_Ch + (size_t)((s+1)&1)*(BSZ*240);
    uint32_t* dstL = g_Cl + (size_t)((s+1)&1)*(BSZ*240);
    float acc[2][2][4];
    ACC_INIT(acc);
    gemm_pipe<15,true>(srcH + (size_t)m0*240, srcL + (size_t)m0*240, 240,
                  g_WdH + (size_t)n0*240, g_WdL + (size_t)n0*240, 240,
                  P, acc, tid, wm, wn, g, tg);
    ACC_TO_CS(acc, cs);
    __syncthreads();
    #pragma unroll 1
    for(int p=tid;p<512;p+=256){
        int m = p>>3, jp = p&7;
        int b = m0+m;
        float4 s0 = *(const float4*)(g_bsD + n0 + 8*jp);
        float4 s1 = *(const float4*)(g_bsD + n0 + 8*jp + 4);
        const float* cp = cs + m*66 + 8*jp;
        float gi0=cp[0]+s0.x, gf0=cp[1]+s0.y, gg0=cp[2]+s0.z, go0=cp[3]+s0.w;
        float gi1=cp[4]+s1.x, gf1=cp[5]+s1.y, gg1=cp[6]+s1.z, go1=cp[7]+s1.w;
        int j0 = (n0>>2) + 2*jp;
        float c0v = g_dc[(size_t)b*HID + j0];
        float c1v = g_dc[(size_t)b*HID + j0 + 1];
        float cc0 = sigm(gf0)*c0v + sigm(gi0)*tanhf(gg0);
        float cc1 = sigm(gf1)*c1v + sigm(gi1)*tanhf(gg1);
        float h0v = sigm(go0)*tanhf(cc0);
        float h1v = sigm(go1)*tanhf(cc1);
        g_dc[(size_t)b*HID + j0]   = cc0;
        g_dc[(size_t)b*HID + j0+1] = cc1;
        g_dh[(size_t)b*HID + j0]   = h0v;
        g_dh[(size_t)b*HID + j0+1] = h1v;
        uint32_t hh,ll; splitpair(h0v,h1v,hh,ll);
        dstH[(size_t)b*240 + 112 + (n0>>3) + jp] = hh;
        dstL[(size_t)b*240 + 112 + (n0>>3) + jp] = ll;
    }
}

// =====================  fused attention + output projection (PDL)  =====================
__global__ __launch_bounds__(256) void attn_out_k(const float* __restrict__ attw,
        const float* __restrict__ attb, const float* __restrict__ outw,
        const float* __restrict__ outb, float* __restrict__ out, int s){
    cudaGridDependencySynchronize();
    int b = blockIdx.x, tid = threadIdx.x;
    __shared__ float dh_s[256];
    __shared__ float red[256];
    __shared__ float sc[TT];
    __shared__ float ctx_s[AD];
    dh_s[tid] = g_dh[(size_t)b*HID + tid];
    __syncthreads();

    if(s < OUT_LEN){
        red[tid] = dh_s[tid]*__ldg(attw+tid);
        __syncthreads();
        #pragma unroll
        for(int r=128;r>0;r>>=1){ if(tid<r) red[tid]+=red[tid+r]; __syncthreads(); }
        float hw = red[0] + __ldg(attb);
        if(tid < 32){
            float x = g_escore[b*TT + tid] + hw;
            float mx = x;
            #pragma unroll
            for(int o=16;o>0;o>>=1) mx = fmaxf(mx,__shfl_xor_sync(0xffffffffu,mx,o));
            float e = expf(x-mx), sm = e;
            #pragma unroll
            for(int o=16;o>0;o>>=1) sm += __shfl_xor_sync(0xffffffffu,sm,o);
            sc[tid] = e/sm;
        }
        __syncthreads();
        if(tid < AD){
            const float* y = g_y8 + (size_t)b*TT*AD + tid;
            float acc=0.f;
            #pragma unroll
            for(int t=0;t<TT;t++) acc = fmaf(sc[t], y[t*AD], acc);
            ctx_s[tid]=acc;
        }
        __syncthreads();
        if(tid < 112){
            uint32_t hh,ll; splitpair(ctx_s[2*tid], ctx_s[2*tid+1], hh, ll);
            g_Ch[(size_t)(s&1)*(BSZ*240) + (size_t)b*240 + tid] = hh;
            g_Cl[(size_t)(s&1)*(BSZ*240) + (size_t)b*240 + tid] = ll;
        }
    }
    if(s > 0){
        int w = tid>>5, lane = tid&31;
        #pragma unroll
        for(int v=w; v<VOCAB; v+=8){
            const float* wp = outw + (size_t)v*HID;
            float sum = 0.f;
            #pragma unroll
            for(int q=0;q<8;q++) sum = fmaf(dh_s[lane+32*q], __ldg(wp+lane+32*q), sum);
            #pragma unroll
            for(int o=16;o>0;o>>=1) sum += __shfl_xor_sync(0xffffffffu,sum,o);
            if(lane==0)
                out[(size_t)b*VOCAB*OUT_LEN + v*OUT_LEN + (s-1)] = sum + __ldg(outb+v);
        }
    }
}

// =====================  launch  =====================
extern "C" void kernel_launch(void* const* d_in, const int* in_sizes, int n_in,
                              void* d_out, int out_size){
    const float* x       = (const float*)d_in[0];
    const float* c1w     = (const float*)d_in[1];
    const float* c1b     = (const float*)d_in[2];
    const float* c2w     = (const float*)d_in[3];
    const float* c2b     = (const float*)d_in[4];
    const float* c3w     = (const float*)d_in[5];
    const float* c3b     = (const float*)d_in[6];
    const float* c4w     = (const float*)d_in[7];
    const float* c4b     = (const float*)d_in[8];
    const float* h0      = (const float*)d_in[9];
    const float* c0      = (const float*)d_in[10];
    const float* lstmWih = (const float*)d_in[11];
    const float* lstmWhh = (const float*)d_in[12];
    const float* lstmbih = (const float*)d_in[13];
    const float* lstmbhh = (const float*)d_in[14];
    const float* attw    = (const float*)d_in[15];
    const float* attb    = (const float*)d_in[16];
    const float* decWih  = (const float*)d_in[17];
    const float* decWhh  = (const float*)d_in[18];
    const float* decbih  = (const float*)d_in[19];
    const float* decbhh  = (const float*)d_in[20];
    const float* outw    = (const float*)d_in[21];
    const float* outb    = (const float*)d_in[22];
    float* out = (float*)d_out;

    float *y1,*y2,*y3,*y5;
    uint32_t *Y5h,*Y5l;
    cudaGetSymbolAddress((void**)&y1,  g_y1);
    cudaGetSymbolAddress((void**)&y2,  g_y2);
    cudaGetSymbolAddress((void**)&y3,  g_y3);
    cudaGetSymbolAddress((void**)&y5,  g_y5);
    cudaGetSymbolAddress((void**)&Y5h, g_Y5h);
    cudaGetSymbolAddress((void**)&Y5l, g_Y5l);

    // merged weight prep (1 launch)
    prep_k<<<(SEG5+255)/256,256>>>(lstmWih, lstmWhh, decWih, decWhh,
                                   lstmbih, lstmbhh, decbih, decbhh);

    // conv stack
    conv1_k<<<BSZ*6,256>>>(x,  c1w, c1b, y1);
    conv2_k<<<BSZ*6,256>>>(y1, c2w, c2b, y2);
    conv3_k<<<BSZ*4,256>>>(y2, c3w, c3b, y3);
    conv4_k<<<BSZ,  256>>>(y3, c4w, c4b, y5);

    // split y5 then xW GEMM
    split_a_k<<<(BSZ*TT*112+255)/256,256>>>(y5, Y5h, Y5l, BSZ*TT*112);
    gemm_x<<<dim3(14,512),256>>>();

    // encoder scan (PDL launches)
    init_enc_k<<<(BSZ*AD+255)/256,256>>>(h0, c0);
    cudaLaunchAttribute pdlAttr[1];
    pdlAttr[0].id = cudaLaunchAttributeProgrammaticStreamSerialization;
    pdlAttr[0].val.programmaticStreamSerializationAllowed = 1;
    for(int t=0;t<TT;t++){
        cudaLaunchConfig_t cfg = {};
        cfg.gridDim = dim3(14,16);
        cfg.blockDim = dim3(256);
        cfg.attrs = pdlAttr;
        cfg.numAttrs = 1;
        cudaLaunchKernelEx(&cfg, enc_step, t);
    }

    // attention precompute + decoder init
    enc_score_k<<<(BSZ*TT*32+255)/256,256>>>(attw);
    init_dec_k<<<(BSZ*HID+255)/256,256>>>();

    // decoder scan (PDL launches): attn(s)+out(s-1), then gemm+cell(s)
    for(int s=0;s<=OUT_LEN;s++){
        {
            cudaLaunchConfig_t cfg = {};
            cfg.gridDim = dim3(BSZ);
            cfg.blockDim = dim3(256);
            cfg.attrs = pdlAttr;
            cfg.numAttrs = 1;
            cudaLaunchKernelEx(&cfg, attn_out_k, attw, attb, outw, outb, out, s);
        }
        if(s<OUT_LEN){
            cudaLaunchConfig_t cfg = {};
            cfg.gridDim = dim3(16,16);
            cfg.blockDim = dim3(256);
            cfg.attrs = pdlAttr;
            cfg.numAttrs = 1;
            cudaLaunchKernelEx(&cfg, dec_step, s);
        }
    }
}